// round 3
// baseline (speedup 1.0000x reference)
#include <cuda_runtime.h>

// Problem constants (B=2, H=8, S=2048, Sm=2047, D=64)
#define B_   2
#define H_   8
#define S_   2048
#define SM_  2047
#define D_   64
#define BH_  16          // B*H

__device__ __forceinline__ float neg_big() { return -1e9f; }
#define INV_T 0.125f     // 1/TEMPERATURE (= 1/8)

// Output layout (floats), tuple order:
// poi_output, time_output, distance_output, attn1, attn2, attn3
#define O_POI   ((size_t)0)
#define O_TIME  ((size_t)2097152)     // + 16*2048*64
#define O_DIST  ((size_t)4193280)     // + 16*2047*64
#define O_A1    ((size_t)6289408)     // + 16*2047*64
#define O_A2    ((size_t)73398272)    // + 16*2048*2048
#define O_A3    ((size_t)140441616)   // + 16*2047*2047

// ---------------------------------------------------------------------------
// Kernel A: masked scaled scores  S = (Q @ K^T) / T  (mask on stream 0)
// 128x128 output tile per block, 256 threads, 8x8 micro-tile, D=64 fully
// resident in shared memory (stored d-major for conflict-free vector reads).
// ---------------------------------------------------------------------------
__global__ __launch_bounds__(256) void scores_kernel(
    const float* __restrict__ pq, const float* __restrict__ pk,
    const float* __restrict__ tq, const float* __restrict__ tk,
    const float* __restrict__ dq, const float* __restrict__ dk,
    const int*   __restrict__ mask, float* __restrict__ out)
{
    __shared__ __align__(16) float Qs[64][132];
    __shared__ __align__(16) float Ks[64][132];

    const int z      = blockIdx.z;
    const int stream = z >> 4;
    const int bh     = z & 15;

    const float *Q, *K;
    float* A;
    int Sq, Sk;
    const int* M = nullptr;

    if (stream == 0) {
        Sq = S_; Sk = S_;
        Q = pq + (size_t)bh * S_ * D_;
        K = pk + (size_t)bh * S_ * D_;
        A = out + O_A1 + (size_t)bh * S_ * S_;
        M = mask + (size_t)(bh >> 3) * S_ * S_;   // b = bh / H
    } else if (stream == 1) {
        Sq = SM_; Sk = SM_;
        Q = tq + (size_t)bh * SM_ * D_;
        K = tk + (size_t)bh * SM_ * D_;
        A = out + O_A2 + (size_t)bh * SM_ * SM_;
    } else {
        Sq = SM_; Sk = SM_;
        Q = dq + (size_t)bh * SM_ * D_;
        K = dk + (size_t)bh * SM_ * D_;
        A = out + O_A3 + (size_t)bh * SM_ * SM_;
    }

    const int q0  = blockIdx.y * 128;
    const int c0  = blockIdx.x * 128;
    const int tid = threadIdx.x;

    // Load tiles (d-major in smem). Consecutive threads take consecutive rows
    // so the 4 scalar smem stores per float4 are bank-conflict-free.
    #pragma unroll 4
    for (int i = tid; i < 128 * 16; i += 256) {
        int row = i & 127;
        int dv  = i >> 7;           // 0..15 -> d = dv*4
        float4 qv = make_float4(0.f, 0.f, 0.f, 0.f);
        float4 kv = make_float4(0.f, 0.f, 0.f, 0.f);
        if (q0 + row < Sq) qv = *(const float4*)(Q + (size_t)(q0 + row) * D_ + dv * 4);
        if (c0 + row < Sk) kv = *(const float4*)(K + (size_t)(c0 + row) * D_ + dv * 4);
        Qs[dv * 4 + 0][row] = qv.x; Qs[dv * 4 + 1][row] = qv.y;
        Qs[dv * 4 + 2][row] = qv.z; Qs[dv * 4 + 3][row] = qv.w;
        Ks[dv * 4 + 0][row] = kv.x; Ks[dv * 4 + 1][row] = kv.y;
        Ks[dv * 4 + 2][row] = kv.z; Ks[dv * 4 + 3][row] = kv.w;
    }
    __syncthreads();

    const int tx = tid & 15;
    const int ty = tid >> 4;

    float acc[8][8];
    #pragma unroll
    for (int i = 0; i < 8; ++i)
        #pragma unroll
        for (int j = 0; j < 8; ++j) acc[i][j] = 0.f;

    #pragma unroll 4
    for (int dd = 0; dd < 64; ++dd) {
        float4 a0 = *(const float4*)&Qs[dd][ty * 8];
        float4 a1 = *(const float4*)&Qs[dd][ty * 8 + 4];
        float4 b0 = *(const float4*)&Ks[dd][tx * 8];
        float4 b1 = *(const float4*)&Ks[dd][tx * 8 + 4];
        float qf[8] = {a0.x, a0.y, a0.z, a0.w, a1.x, a1.y, a1.z, a1.w};
        float kf[8] = {b0.x, b0.y, b0.z, b0.w, b1.x, b1.y, b1.z, b1.w};
        #pragma unroll
        for (int i = 0; i < 8; ++i)
            #pragma unroll
            for (int j = 0; j < 8; ++j)
                acc[i][j] = fmaf(qf[i], kf[j], acc[i][j]);
    }

    #pragma unroll
    for (int i = 0; i < 8; ++i) {
        int qq = q0 + ty * 8 + i;
        if (qq >= Sq) break;
        size_t rowbase = (size_t)qq * Sk;
        #pragma unroll
        for (int j = 0; j < 8; ++j) {
            int cc = c0 + tx * 8 + j;
            if (cc >= Sk) break;
            float s = acc[i][j] * INV_T;
            if (M && M[(size_t)qq * S_ + cc] == 0) s = neg_big();
            A[rowbase + cc] = s;
        }
    }
}

// ---------------------------------------------------------------------------
// Kernel B: in-place row softmax over the attn buffers.
// One block of 256 threads per row; row (<=2048 floats) cached in registers.
// ---------------------------------------------------------------------------
__global__ __launch_bounds__(256) void softmax_kernel(float* __restrict__ out)
{
    const int row    = blockIdx.x;
    const int z      = blockIdx.y;
    const int stream = z >> 4;
    const int bh     = z & 15;

    int Sk;
    float* A;
    if (stream == 0)      { Sk = S_;  A = out + O_A1 + (size_t)bh * S_  * S_;  }
    else if (stream == 1) { Sk = SM_; A = out + O_A2 + (size_t)bh * SM_ * SM_; }
    else                  { Sk = SM_; A = out + O_A3 + (size_t)bh * SM_ * SM_; }
    if (row >= Sk) return;                 // Sq == Sk for every stream

    float* r = A + (size_t)row * Sk;
    const int tid = threadIdx.x;

    float v[8];
    #pragma unroll
    for (int u = 0; u < 8; ++u) {
        int i = u * 256 + tid;
        v[u] = (i < Sk) ? r[i] : -3.0e38f;
    }

    // ---- block max ----
    float m = v[0];
    #pragma unroll
    for (int u = 1; u < 8; ++u) m = fmaxf(m, v[u]);
    #pragma unroll
    for (int o = 16; o > 0; o >>= 1) m = fmaxf(m, __shfl_xor_sync(0xffffffffu, m, o));

    __shared__ float sm[8];
    const int w = tid >> 5, l = tid & 31;
    if (l == 0) sm[w] = m;
    __syncthreads();
    if (tid < 32) {
        float t = (tid < 8) ? sm[tid] : -3.0e38f;
        #pragma unroll
        for (int o = 4; o > 0; o >>= 1) t = fmaxf(t, __shfl_xor_sync(0xffffffffu, t, o));
        if (tid == 0) sm[0] = t;
    }
    __syncthreads();
    m = sm[0];
    __syncthreads();

    // ---- exp + block sum ----
    float s = 0.f;
    #pragma unroll
    for (int u = 0; u < 8; ++u) {
        v[u] = __expf(v[u] - m);           // padded lanes -> exp(-inf) = 0
        s += v[u];
    }
    #pragma unroll
    for (int o = 16; o > 0; o >>= 1) s += __shfl_xor_sync(0xffffffffu, s, o);
    if (l == 0) sm[w] = s;
    __syncthreads();
    if (tid < 32) {
        float t = (tid < 8) ? sm[tid] : 0.f;
        #pragma unroll
        for (int o = 4; o > 0; o >>= 1) t += __shfl_xor_sync(0xffffffffu, t, o);
        if (tid == 0) sm[0] = t;
    }
    __syncthreads();
    const float inv = 1.0f / sm[0];

    #pragma unroll
    for (int u = 0; u < 8; ++u) {
        int i = u * 256 + tid;
        if (i < Sk) r[i] = v[u] * inv;
    }
}

// ---------------------------------------------------------------------------
// Kernel C: O = P @ V  (optionally P+P2, optionally accumulated into O).
// 256 rows x 64 cols per block, K-chunks of 32, 256 threads, 8x8 micro-tile.
// jobs: 0 attn1@poi_v -> poi_out (store)
//       1 attn2@time_v -> time_out (store)
//       2 attn3@dist_v -> dist_out (store)
//       3 (attn2+attn3)@poi_v[:-1] -> poi_out[1:] (accumulate)
// ---------------------------------------------------------------------------
__global__ __launch_bounds__(256) void pv_kernel(
    const float* __restrict__ pv, const float* __restrict__ tv,
    const float* __restrict__ dvv, float* __restrict__ out, int job_base)
{
    __shared__ float Ps[256][33];
    __shared__ __align__(16) float Vs[32][68];

    const int z   = blockIdx.z;
    const int job = job_base + (z >> 4);
    const int bh  = z & 15;

    const float *P, *P2 = nullptr, *V;
    float* O;
    int Sq, Sk;
    bool accum = false;

    if (job == 0) {
        Sq = S_; Sk = S_;
        P = out + O_A1 + (size_t)bh * S_ * S_;
        V = pv + (size_t)bh * S_ * D_;
        O = out + O_POI + (size_t)bh * S_ * D_;
    } else if (job == 1) {
        Sq = SM_; Sk = SM_;
        P = out + O_A2 + (size_t)bh * SM_ * SM_;
        V = tv + (size_t)bh * SM_ * D_;
        O = out + O_TIME + (size_t)bh * SM_ * D_;
    } else if (job == 2) {
        Sq = SM_; Sk = SM_;
        P = out + O_A3 + (size_t)bh * SM_ * SM_;
        V = dvv + (size_t)bh * SM_ * D_;
        O = out + O_DIST + (size_t)bh * SM_ * D_;
    } else {
        Sq = SM_; Sk = SM_;
        P  = out + O_A2 + (size_t)bh * SM_ * SM_;
        P2 = out + O_A3 + (size_t)bh * SM_ * SM_;
        V  = pv + (size_t)bh * S_ * D_;             // rows 0..2046 = poi_v[:-1]
        O  = out + O_POI + (size_t)bh * S_ * D_ + D_;  // shifted by one row
        accum = true;
    }

    const int r0   = blockIdx.x * 256;
    const int tid  = threadIdx.x;
    const int rowt = tid >> 3;       // 0..31 -> 8 rows each
    const int colt = tid & 7;        // 0..7  -> 8 cols each

    float acc[8][8];
    #pragma unroll
    for (int i = 0; i < 8; ++i)
        #pragma unroll
        for (int j = 0; j < 8; ++j) acc[i][j] = 0.f;

    for (int ck = 0; ck < Sk; ck += 32) {
        // load P chunk (coalesced along k), optional P2 add
        #pragma unroll 8
        for (int it = 0; it < 32; ++it) {
            int i  = it * 256 + tid;
            int kk = i & 31, rr = i >> 5;
            int gr = r0 + rr, gk = ck + kk;
            float p = 0.f;
            if (gr < Sq && gk < Sk) {
                size_t idx = (size_t)gr * Sk + gk;
                p = P[idx];
                if (P2) p += P2[idx];
            }
            Ps[rr][kk] = p;
        }
        // load V chunk (coalesced along d)
        #pragma unroll
        for (int it = 0; it < 8; ++it) {
            int i  = it * 256 + tid;
            int dd = i & 63, kk = i >> 6;
            int gk = ck + kk;
            Vs[kk][dd] = (gk < Sk) ? V[(size_t)gk * D_ + dd] : 0.f;
        }
        __syncthreads();

        #pragma unroll 4
        for (int kk = 0; kk < 32; ++kk) {
            float pf[8];
            #pragma unroll
            for (int i = 0; i < 8; ++i) pf[i] = Ps[rowt * 8 + i][kk];
            float4 v0 = *(const float4*)&Vs[kk][colt * 8];
            float4 v1 = *(const float4*)&Vs[kk][colt * 8 + 4];
            float vf[8] = {v0.x, v0.y, v0.z, v0.w, v1.x, v1.y, v1.z, v1.w};
            #pragma unroll
            for (int i = 0; i < 8; ++i)
                #pragma unroll
                for (int j = 0; j < 8; ++j)
                    acc[i][j] = fmaf(pf[i], vf[j], acc[i][j]);
        }
        __syncthreads();
    }

    #pragma unroll
    for (int i = 0; i < 8; ++i) {
        int gr = r0 + rowt * 8 + i;
        if (gr >= Sq) break;
        size_t base = (size_t)gr * D_ + colt * 8;
        if (accum) {
            #pragma unroll
            for (int j = 0; j < 8; ++j) O[base + j] += acc[i][j];
        } else {
            #pragma unroll
            for (int j = 0; j < 8; ++j) O[base + j] = acc[i][j];
        }
    }
}

// ---------------------------------------------------------------------------
extern "C" void kernel_launch(void* const* d_in, const int* in_sizes, int n_in,
                              void* d_out, int out_size)
{
    const float* pq  = (const float*)d_in[0];
    const float* pk  = (const float*)d_in[1];
    const float* pv  = (const float*)d_in[2];
    const float* tq  = (const float*)d_in[3];
    const float* tk  = (const float*)d_in[4];
    const float* tv  = (const float*)d_in[5];
    const float* dq  = (const float*)d_in[6];
    const float* dk  = (const float*)d_in[7];
    const float* dvv = (const float*)d_in[8];
    const int*   msk = (const int*)d_in[9];
    float* out = (float*)d_out;

    // A: scores (+ mask for stream 0)
    scores_kernel<<<dim3(16, 16, 48), 256>>>(pq, pk, tq, tk, dq, dk, msk, out);
    // B: row softmax, in place in the attn output buffers
    softmax_kernel<<<dim3(2048, 48), 256>>>(out);
    // C: direct P@V outputs (jobs 0..2)
    pv_kernel<<<dim3(8, 1, 48), 256>>>(pv, tv, dvv, out, 0);
    // C: cross term (job 3), must come after job 0's store (stream-ordered)
    pv_kernel<<<dim3(8, 1, 16), 256>>>(pv, tv, dvv, out, 3);
}

// round 4
// speedup vs baseline: 1.0203x; 1.0203x over previous
#include <cuda_runtime.h>

// Problem constants (B=2, H=8, S=2048, Sm=2047, D=64)
#define B_   2
#define H_   8
#define S_   2048
#define SM_  2047
#define D_   64
#define BH_  16          // B*H

__device__ __forceinline__ float neg_big() { return -1e9f; }
#define INV_T 0.125f     // 1/TEMPERATURE (= 1/8)

// Output layout (floats), tuple order:
// poi_output, time_output, distance_output, attn1, attn2, attn3
#define O_POI   ((size_t)0)
#define O_TIME  ((size_t)2097152)     // + 16*2048*64
#define O_DIST  ((size_t)4193280)     // + 16*2047*64
#define O_A1    ((size_t)6289408)     // + 16*2047*64
#define O_A2    ((size_t)73398272)    // + 16*2048*2048
#define O_A3    ((size_t)140441616)   // + 16*2047*2047

// ---------------------------------------------------------------------------
// Kernel A: masked scaled scores  S = (Q @ K^T) / T  (mask on stream 0)
// 128x128 output tile per block, 256 threads, 8x8 micro-tile, D=64 fully
// resident in shared memory (stored d-major for conflict-free vector reads).
// ---------------------------------------------------------------------------
__global__ __launch_bounds__(256) void scores_kernel(
    const float* __restrict__ pq, const float* __restrict__ pk,
    const float* __restrict__ tq, const float* __restrict__ tk,
    const float* __restrict__ dq, const float* __restrict__ dk,
    const int*   __restrict__ mask, float* __restrict__ out)
{
    __shared__ __align__(16) float Qs[64][132];
    __shared__ __align__(16) float Ks[64][132];

    const int z      = blockIdx.z;
    const int stream = z >> 4;
    const int bh     = z & 15;

    const float *Q, *K;
    float* A;
    int Sq, Sk;
    const int* M = nullptr;

    if (stream == 0) {
        Sq = S_; Sk = S_;
        Q = pq + (size_t)bh * S_ * D_;
        K = pk + (size_t)bh * S_ * D_;
        A = out + O_A1 + (size_t)bh * S_ * S_;
        M = mask + (size_t)(bh >> 3) * S_ * S_;   // b = bh / H
    } else if (stream == 1) {
        Sq = SM_; Sk = SM_;
        Q = tq + (size_t)bh * SM_ * D_;
        K = tk + (size_t)bh * SM_ * D_;
        A = out + O_A2 + (size_t)bh * SM_ * SM_;
    } else {
        Sq = SM_; Sk = SM_;
        Q = dq + (size_t)bh * SM_ * D_;
        K = dk + (size_t)bh * SM_ * D_;
        A = out + O_A3 + (size_t)bh * SM_ * SM_;
    }

    const int q0  = blockIdx.y * 128;
    const int c0  = blockIdx.x * 128;
    const int tid = threadIdx.x;

    // Load tiles (d-major in smem). Consecutive threads take consecutive rows
    // so the 4 scalar smem stores per float4 are bank-conflict-free.
    #pragma unroll 4
    for (int i = tid; i < 128 * 16; i += 256) {
        int row = i & 127;
        int dv  = i >> 7;           // 0..15 -> d = dv*4
        float4 qv = make_float4(0.f, 0.f, 0.f, 0.f);
        float4 kv = make_float4(0.f, 0.f, 0.f, 0.f);
        if (q0 + row < Sq) qv = *(const float4*)(Q + (size_t)(q0 + row) * D_ + dv * 4);
        if (c0 + row < Sk) kv = *(const float4*)(K + (size_t)(c0 + row) * D_ + dv * 4);
        Qs[dv * 4 + 0][row] = qv.x; Qs[dv * 4 + 1][row] = qv.y;
        Qs[dv * 4 + 2][row] = qv.z; Qs[dv * 4 + 3][row] = qv.w;
        Ks[dv * 4 + 0][row] = kv.x; Ks[dv * 4 + 1][row] = kv.y;
        Ks[dv * 4 + 2][row] = kv.z; Ks[dv * 4 + 3][row] = kv.w;
    }
    __syncthreads();

    const int tx = tid & 15;
    const int ty = tid >> 4;

    float acc[8][8];
    #pragma unroll
    for (int i = 0; i < 8; ++i)
        #pragma unroll
        for (int j = 0; j < 8; ++j) acc[i][j] = 0.f;

    #pragma unroll 4
    for (int dd = 0; dd < 64; ++dd) {
        float4 a0 = *(const float4*)&Qs[dd][ty * 8];
        float4 a1 = *(const float4*)&Qs[dd][ty * 8 + 4];
        float4 b0 = *(const float4*)&Ks[dd][tx * 8];
        float4 b1 = *(const float4*)&Ks[dd][tx * 8 + 4];
        float qf[8] = {a0.x, a0.y, a0.z, a0.w, a1.x, a1.y, a1.z, a1.w};
        float kf[8] = {b0.x, b0.y, b0.z, b0.w, b1.x, b1.y, b1.z, b1.w};
        #pragma unroll
        for (int i = 0; i < 8; ++i)
            #pragma unroll
            for (int j = 0; j < 8; ++j)
                acc[i][j] = fmaf(qf[i], kf[j], acc[i][j]);
    }

    #pragma unroll
    for (int i = 0; i < 8; ++i) {
        int qq = q0 + ty * 8 + i;
        if (qq >= Sq) break;
        size_t rowbase = (size_t)qq * Sk;
        #pragma unroll
        for (int j = 0; j < 8; ++j) {
            int cc = c0 + tx * 8 + j;
            if (cc >= Sk) break;
            float s = acc[i][j] * INV_T;
            if (M && M[(size_t)qq * S_ + cc] == 0) s = neg_big();
            A[rowbase + cc] = s;
        }
    }
}

// ---------------------------------------------------------------------------
// Kernel B: in-place row softmax over the attn buffers.
// One block of 256 threads per row; row (<=2048 floats) cached in registers.
// ---------------------------------------------------------------------------
__global__ __launch_bounds__(256) void softmax_kernel(float* __restrict__ out)
{
    const int row    = blockIdx.x;
    const int z      = blockIdx.y;
    const int stream = z >> 4;
    const int bh     = z & 15;

    int Sk;
    float* A;
    if (stream == 0)      { Sk = S_;  A = out + O_A1 + (size_t)bh * S_  * S_;  }
    else if (stream == 1) { Sk = SM_; A = out + O_A2 + (size_t)bh * SM_ * SM_; }
    else                  { Sk = SM_; A = out + O_A3 + (size_t)bh * SM_ * SM_; }
    if (row >= Sk) return;                 // Sq == Sk for every stream

    float* r = A + (size_t)row * Sk;
    const int tid = threadIdx.x;

    float v[8];
    #pragma unroll
    for (int u = 0; u < 8; ++u) {
        int i = u * 256 + tid;
        v[u] = (i < Sk) ? r[i] : -3.0e38f;
    }

    // ---- block max ----
    float m = v[0];
    #pragma unroll
    for (int u = 1; u < 8; ++u) m = fmaxf(m, v[u]);
    #pragma unroll
    for (int o = 16; o > 0; o >>= 1) m = fmaxf(m, __shfl_xor_sync(0xffffffffu, m, o));

    __shared__ float sm[8];
    const int w = tid >> 5, l = tid & 31;
    if (l == 0) sm[w] = m;
    __syncthreads();
    if (tid < 32) {
        float t = (tid < 8) ? sm[tid] : -3.0e38f;
        #pragma unroll
        for (int o = 4; o > 0; o >>= 1) t = fmaxf(t, __shfl_xor_sync(0xffffffffu, t, o));
        if (tid == 0) sm[0] = t;
    }
    __syncthreads();
    m = sm[0];
    __syncthreads();

    // ---- exp + block sum ----
    float s = 0.f;
    #pragma unroll
    for (int u = 0; u < 8; ++u) {
        v[u] = __expf(v[u] - m);           // padded lanes -> exp(-inf) = 0
        s += v[u];
    }
    #pragma unroll
    for (int o = 16; o > 0; o >>= 1) s += __shfl_xor_sync(0xffffffffu, s, o);
    if (l == 0) sm[w] = s;
    __syncthreads();
    if (tid < 32) {
        float t = (tid < 8) ? sm[tid] : 0.f;
        #pragma unroll
        for (int o = 4; o > 0; o >>= 1) t += __shfl_xor_sync(0xffffffffu, t, o);
        if (tid == 0) sm[0] = t;
    }
    __syncthreads();
    const float inv = 1.0f / sm[0];

    #pragma unroll
    for (int u = 0; u < 8; ++u) {
        int i = u * 256 + tid;
        if (i < Sk) r[i] = v[u] * inv;
    }
}

// ---------------------------------------------------------------------------
// Kernel C: O = P @ V  (optionally P+P2, optionally accumulated into O).
// 256 rows x 64 cols per block, K-chunks of 32, 256 threads, 8x8 micro-tile.
// jobs: 0 attn1@poi_v -> poi_out (store)
//       1 attn2@time_v -> time_out (store)
//       2 attn3@dist_v -> dist_out (store)
//       3 (attn2+attn3)@poi_v[:-1] -> poi_out[1:] (accumulate)
// ---------------------------------------------------------------------------
__global__ __launch_bounds__(256) void pv_kernel(
    const float* __restrict__ pv, const float* __restrict__ tv,
    const float* __restrict__ dvv, float* __restrict__ out, int job_base)
{
    __shared__ float Ps[256][33];
    __shared__ __align__(16) float Vs[32][68];

    const int z   = blockIdx.z;
    const int job = job_base + (z >> 4);
    const int bh  = z & 15;

    const float *P, *P2 = nullptr, *V;
    float* O;
    int Sq, Sk;
    bool accum = false;

    if (job == 0) {
        Sq = S_; Sk = S_;
        P = out + O_A1 + (size_t)bh * S_ * S_;
        V = pv + (size_t)bh * S_ * D_;
        O = out + O_POI + (size_t)bh * S_ * D_;
    } else if (job == 1) {
        Sq = SM_; Sk = SM_;
        P = out + O_A2 + (size_t)bh * SM_ * SM_;
        V = tv + (size_t)bh * SM_ * D_;
        O = out + O_TIME + (size_t)bh * SM_ * D_;
    } else if (job == 2) {
        Sq = SM_; Sk = SM_;
        P = out + O_A3 + (size_t)bh * SM_ * SM_;
        V = dvv + (size_t)bh * SM_ * D_;
        O = out + O_DIST + (size_t)bh * SM_ * D_;
    } else {
        Sq = SM_; Sk = SM_;
        P  = out + O_A2 + (size_t)bh * SM_ * SM_;
        P2 = out + O_A3 + (size_t)bh * SM_ * SM_;
        V  = pv + (size_t)bh * S_ * D_;             // rows 0..2046 = poi_v[:-1]
        O  = out + O_POI + (size_t)bh * S_ * D_ + D_;  // shifted by one row
        accum = true;
    }

    const int r0   = blockIdx.x * 256;
    const int tid  = threadIdx.x;
    const int rowt = tid >> 3;       // 0..31 -> 8 rows each
    const int colt = tid & 7;        // 0..7  -> 8 cols each

    float acc[8][8];
    #pragma unroll
    for (int i = 0; i < 8; ++i)
        #pragma unroll
        for (int j = 0; j < 8; ++j) acc[i][j] = 0.f;

    for (int ck = 0; ck < Sk; ck += 32) {
        // load P chunk (coalesced along k), optional P2 add
        #pragma unroll 8
        for (int it = 0; it < 32; ++it) {
            int i  = it * 256 + tid;
            int kk = i & 31, rr = i >> 5;
            int gr = r0 + rr, gk = ck + kk;
            float p = 0.f;
            if (gr < Sq && gk < Sk) {
                size_t idx = (size_t)gr * Sk + gk;
                p = P[idx];
                if (P2) p += P2[idx];
            }
            Ps[rr][kk] = p;
        }
        // load V chunk (coalesced along d)
        #pragma unroll
        for (int it = 0; it < 8; ++it) {
            int i  = it * 256 + tid;
            int dd = i & 63, kk = i >> 6;
            int gk = ck + kk;
            Vs[kk][dd] = (gk < Sk) ? V[(size_t)gk * D_ + dd] : 0.f;
        }
        __syncthreads();

        #pragma unroll 4
        for (int kk = 0; kk < 32; ++kk) {
            float pf[8];
            #pragma unroll
            for (int i = 0; i < 8; ++i) pf[i] = Ps[rowt * 8 + i][kk];
            float4 v0 = *(const float4*)&Vs[kk][colt * 8];
            float4 v1 = *(const float4*)&Vs[kk][colt * 8 + 4];
            float vf[8] = {v0.x, v0.y, v0.z, v0.w, v1.x, v1.y, v1.z, v1.w};
            #pragma unroll
            for (int i = 0; i < 8; ++i)
                #pragma unroll
                for (int j = 0; j < 8; ++j)
                    acc[i][j] = fmaf(pf[i], vf[j], acc[i][j]);
        }
        __syncthreads();
    }

    #pragma unroll
    for (int i = 0; i < 8; ++i) {
        int gr = r0 + rowt * 8 + i;
        if (gr >= Sq) break;
        size_t base = (size_t)gr * D_ + colt * 8;
        if (accum) {
            #pragma unroll
            for (int j = 0; j < 8; ++j) O[base + j] += acc[i][j];
        } else {
            #pragma unroll
            for (int j = 0; j < 8; ++j) O[base + j] = acc[i][j];
        }
    }
}

// ---------------------------------------------------------------------------
extern "C" void kernel_launch(void* const* d_in, const int* in_sizes, int n_in,
                              void* d_out, int out_size)
{
    const float* pq  = (const float*)d_in[0];
    const float* pk  = (const float*)d_in[1];
    const float* pv  = (const float*)d_in[2];
    const float* tq  = (const float*)d_in[3];
    const float* tk  = (const float*)d_in[4];
    const float* tv  = (const float*)d_in[5];
    const float* dq  = (const float*)d_in[6];
    const float* dk  = (const float*)d_in[7];
    const float* dvv = (const float*)d_in[8];
    const int*   msk = (const int*)d_in[9];
    float* out = (float*)d_out;

    // A: scores (+ mask for stream 0)
    scores_kernel<<<dim3(16, 16, 48), 256>>>(pq, pk, tq, tk, dq, dk, msk, out);
    // B: row softmax, in place in the attn output buffers
    softmax_kernel<<<dim3(2048, 48), 256>>>(out);
    // C: direct P@V outputs (jobs 0..2)
    pv_kernel<<<dim3(8, 1, 48), 256>>>(pv, tv, dvv, out, 0);
    // C: cross term (job 3), must come after job 0's store (stream-ordered)
    pv_kernel<<<dim3(8, 1, 16), 256>>>(pv, tv, dvv, out, 3);
}

// round 6
// speedup vs baseline: 1.9423x; 1.9037x over previous
#include <cuda_runtime.h>
#include <cuda_bf16.h>
#include <cuda_fp16.h>
#include <cstdint>

#define S_   2048
#define SM_  2047
#define NEGV (-1e9f)

// Output layout (floats): poi, time, dist, attn1, attn2, attn3
#define O_POI   ((size_t)0)
#define O_TIME  ((size_t)2097152)
#define O_DIST  ((size_t)4193280)
#define O_A1    ((size_t)6289408)
#define O_A2    ((size_t)73398272)
#define O_A3    ((size_t)140441616)

// ---------------- warp-MMA helpers (plain PTX, works on .target sm_103) ----
__device__ __forceinline__ uint32_t smem_u32(const void* p) {
    uint32_t a;
    asm("{ .reg .u64 t; cvta.to.shared.u64 t, %1; cvt.u32.u64 %0, t; }" : "=r"(a) : "l"(p));
    return a;
}
__device__ __forceinline__ void ldm4(uint32_t* r, uint32_t addr) {
    asm volatile("ldmatrix.sync.aligned.m8n8.x4.shared.b16 {%0,%1,%2,%3}, [%4];"
                 : "=r"(r[0]), "=r"(r[1]), "=r"(r[2]), "=r"(r[3]) : "r"(addr));
}
__device__ __forceinline__ void ldm4t(uint32_t* r, uint32_t addr) {
    asm volatile("ldmatrix.sync.aligned.m8n8.x4.trans.shared.b16 {%0,%1,%2,%3}, [%4];"
                 : "=r"(r[0]), "=r"(r[1]), "=r"(r[2]), "=r"(r[3]) : "r"(addr));
}
__device__ __forceinline__ void mma_bf16(float* c, const uint32_t* a, const uint32_t* b) {
    asm volatile("mma.sync.aligned.m16n8k16.row.col.f32.bf16.bf16.f32 "
                 "{%0,%1,%2,%3}, {%4,%5,%6,%7}, {%8,%9}, {%0,%1,%2,%3};"
                 : "+f"(c[0]), "+f"(c[1]), "+f"(c[2]), "+f"(c[3])
                 : "r"(a[0]), "r"(a[1]), "r"(a[2]), "r"(a[3]), "r"(b[0]), "r"(b[1]));
}
__device__ __forceinline__ void mma_f16(float* c, const uint32_t* a, const uint32_t* b) {
    asm volatile("mma.sync.aligned.m16n8k16.row.col.f32.f16.f16.f32 "
                 "{%0,%1,%2,%3}, {%4,%5,%6,%7}, {%8,%9}, {%0,%1,%2,%3};"
                 : "+f"(c[0]), "+f"(c[1]), "+f"(c[2]), "+f"(c[3])
                 : "r"(a[0]), "r"(a[1]), "r"(a[2]), "r"(a[3]), "r"(b[0]), "r"(b[1]));
}
__device__ __forceinline__ void split2(float a, float b, uint32_t& hi, uint32_t& lo) {
    __nv_bfloat16 ha = __float2bfloat16(a), hb = __float2bfloat16(b);
    float la = a - __bfloat162float(ha), lb = b - __bfloat162float(hb);
    __nv_bfloat162 hh; hh.x = ha; hh.y = hb;
    hi = *reinterpret_cast<uint32_t*>(&hh);
    __nv_bfloat162 ll = __floats2bfloat162_rn(la, lb);
    lo = *reinterpret_cast<uint32_t*>(&ll);
}
__device__ __forceinline__ uint32_t ph2(float a, float b) {
    __half2 h = __floats2half2_rn(a, b);
    return *reinterpret_cast<uint32_t*>(&h);
}

// ---------------------------------------------------------------------------
// K1: logits via bf16 3-split mma.sync (block tile 128x128, K=192).
// smem: A [128][200] bf16 (400B rows) @0, B same @51200. Dynamic 102400 B.
// A row = [qh(64) | qh(64) | ql(64)], B row = [kh | kl | kh].
// ---------------------------------------------------------------------------
__global__ __launch_bounds__(256) void qk_kernel(
    const float* __restrict__ pq, const float* __restrict__ pk,
    const float* __restrict__ tq, const float* __restrict__ tk,
    const float* __restrict__ dq, const float* __restrict__ dk,
    const int* __restrict__ mask, float* __restrict__ out)
{
    extern __shared__ __align__(16) char smc[];
    const uint32_t sb = smem_u32(smc);

    const int tid = threadIdx.x, lid = tid & 31, wid = tid >> 5;
    const int z = blockIdx.z, s = z >> 4, bh = z & 15;
    const int Sq = s ? SM_ : S_, Sk = Sq;
    const int m0 = blockIdx.y * 128, n0 = blockIdx.x * 128;

    const float* Qg = ((s == 0) ? pq : (s == 1) ? tq : dq) + (size_t)bh * Sq * 64;
    const float* Kg = ((s == 0) ? pk : (s == 1) ? tk : dk) + (size_t)bh * Sq * 64;
    float* Aout = (s == 0) ? out + O_A1 + (size_t)bh * S_ * S_
                : (s == 1) ? out + O_A2 + (size_t)bh * SM_ * SM_
                           : out + O_A3 + (size_t)bh * SM_ * SM_;
    const int* M = (s == 0) ? mask + (size_t)(bh >> 3) * S_ * S_ : nullptr;

    // stage Q,K -> split bf16 smem
    #pragma unroll
    for (int it = 0; it < 8; ++it) {
        int i = it * 256 + tid;           // 2048 slots
        int row = i >> 4, c4 = (i & 15) << 2;
        float4 qv = make_float4(0.f, 0.f, 0.f, 0.f);
        float4 kv = make_float4(0.f, 0.f, 0.f, 0.f);
        if (m0 + row < Sq) qv = *(const float4*)(Qg + (size_t)(m0 + row) * 64 + c4);
        if (n0 + row < Sk) kv = *(const float4*)(Kg + (size_t)(n0 + row) * 64 + c4);
        qv.x *= 0.125f; qv.y *= 0.125f; qv.z *= 0.125f; qv.w *= 0.125f;
        uint32_t h01, h23, l01, l23;
        uint32_t off = (uint32_t)(row * 400 + c4 * 2);
        split2(qv.x, qv.y, h01, l01); split2(qv.z, qv.w, h23, l23);
        *(uint32_t*)(smc + off)       = h01; *(uint32_t*)(smc + off + 4)   = h23;
        *(uint32_t*)(smc + off + 128) = h01; *(uint32_t*)(smc + off + 132) = h23;
        *(uint32_t*)(smc + off + 256) = l01; *(uint32_t*)(smc + off + 260) = l23;
        split2(kv.x, kv.y, h01, l01); split2(kv.z, kv.w, h23, l23);
        char* bB = smc + 51200;
        *(uint32_t*)(bB + off)       = h01; *(uint32_t*)(bB + off + 4)   = h23;
        *(uint32_t*)(bB + off + 128) = l01; *(uint32_t*)(bB + off + 132) = l23;
        *(uint32_t*)(bB + off + 256) = h01; *(uint32_t*)(bB + off + 260) = h23;
    }
    __syncthreads();

    const int wm = wid & 3, wn = wid >> 2;   // 4 x 2 warp grid: 32m x 64n per warp
    float acc[16][4];
    #pragma unroll
    for (int t = 0; t < 16; ++t)
        #pragma unroll
        for (int j = 0; j < 4; ++j) acc[t][j] = 0.f;

    #pragma unroll
    for (int ks = 0; ks < 12; ++ks) {
        uint32_t a[2][4];
        #pragma unroll
        for (int mi = 0; mi < 2; ++mi) {
            int row = wm * 32 + mi * 16 + (lid & 15);
            ldm4(a[mi], sb + row * 400 + ks * 32 + ((lid >> 4) << 4));
        }
        uint32_t b[8][2];
        #pragma unroll
        for (int nb2 = 0; nb2 < 4; ++nb2) {
            int row = wn * 64 + nb2 * 16 + ((lid >> 4) << 3) + (lid & 7);
            uint32_t r4[4];
            ldm4(r4, sb + 51200 + row * 400 + ks * 32 + (((lid >> 3) & 1) << 4));
            b[nb2 * 2][0] = r4[0]; b[nb2 * 2][1] = r4[1];
            b[nb2 * 2 + 1][0] = r4[2]; b[nb2 * 2 + 1][1] = r4[3];
        }
        #pragma unroll
        for (int mi = 0; mi < 2; ++mi)
            #pragma unroll
            for (int nj = 0; nj < 8; ++nj)
                mma_bf16(acc[mi * 8 + nj], a[mi], b[nj]);
    }

    // epilogue: mask + store
    const int lrow = lid >> 2, lcol = (lid & 3) * 2;
    #pragma unroll
    for (int mi = 0; mi < 2; ++mi) {
        #pragma unroll
        for (int h = 0; h < 2; ++h) {
            int q = m0 + wm * 32 + mi * 16 + h * 8 + lrow;
            if (q >= Sq) continue;
            float* orow = Aout + (size_t)q * Sk;
            if (M) {
                const int* Mrow = M + (size_t)q * S_;
                #pragma unroll
                for (int nj = 0; nj < 8; ++nj) {
                    int cg = n0 + wn * 64 + nj * 8 + lcol;
                    int2 mv = *(const int2*)(Mrow + cg);
                    float2 f;
                    f.x = mv.x ? acc[mi * 8 + nj][h * 2]     : NEGV;
                    f.y = mv.y ? acc[mi * 8 + nj][h * 2 + 1] : NEGV;
                    *(float2*)(orow + cg) = f;
                }
            } else {
                #pragma unroll
                for (int nj = 0; nj < 8; ++nj) {
                    int cg = n0 + wn * 64 + nj * 8 + lcol;
                    if (cg < Sk)     orow[cg]     = acc[mi * 8 + nj][h * 2];
                    if (cg + 1 < Sk) orow[cg + 1] = acc[mi * 8 + nj][h * 2 + 1];
                }
            }
        }
    }
}

// ---------------------------------------------------------------------------
// K2: row softmax in place.
// ---------------------------------------------------------------------------
__global__ __launch_bounds__(256) void softmax_kernel(float* __restrict__ out)
{
    const int row = blockIdx.x, z = blockIdx.y, stream = z >> 4, bh = z & 15;
    int Sk; float* A;
    if (stream == 0)      { Sk = S_;  A = out + O_A1 + (size_t)bh * S_  * S_;  }
    else if (stream == 1) { Sk = SM_; A = out + O_A2 + (size_t)bh * SM_ * SM_; }
    else                  { Sk = SM_; A = out + O_A3 + (size_t)bh * SM_ * SM_; }
    if (row >= Sk) return;

    float* r = A + (size_t)row * Sk;
    const int tid = threadIdx.x;
    float v[8];
    #pragma unroll
    for (int u = 0; u < 8; ++u) {
        int i = u * 256 + tid;
        v[u] = (i < Sk) ? r[i] : -3.0e38f;
    }
    float m = v[0];
    #pragma unroll
    for (int u = 1; u < 8; ++u) m = fmaxf(m, v[u]);
    #pragma unroll
    for (int o = 16; o > 0; o >>= 1) m = fmaxf(m, __shfl_xor_sync(0xffffffffu, m, o));
    __shared__ float smr[8];
    const int w = tid >> 5, l = tid & 31;
    if (l == 0) smr[w] = m;
    __syncthreads();
    if (tid < 32) {
        float t = (tid < 8) ? smr[tid] : -3.0e38f;
        #pragma unroll
        for (int o = 4; o > 0; o >>= 1) t = fmaxf(t, __shfl_xor_sync(0xffffffffu, t, o));
        if (tid == 0) smr[0] = t;
    }
    __syncthreads();
    m = smr[0];
    __syncthreads();
    float sacc = 0.f;
    #pragma unroll
    for (int u = 0; u < 8; ++u) { v[u] = __expf(v[u] - m); sacc += v[u]; }
    #pragma unroll
    for (int o = 16; o > 0; o >>= 1) sacc += __shfl_xor_sync(0xffffffffu, sacc, o);
    if (l == 0) smr[w] = sacc;
    __syncthreads();
    if (tid < 32) {
        float t = (tid < 8) ? smr[tid] : 0.f;
        #pragma unroll
        for (int o = 4; o > 0; o >>= 1) t += __shfl_xor_sync(0xffffffffu, t, o);
        if (tid == 0) smr[0] = t;
    }
    __syncthreads();
    const float inv = 1.0f / smr[0];
    #pragma unroll
    for (int u = 0; u < 8; ++u) {
        int i = u * 256 + tid;
        if (i < Sk) r[i] = v[u] * inv;
    }
}

// ---------------------------------------------------------------------------
// K3: O = P @ V via fp16 mma.sync (tile 128m x 64n, K chunks of 64).
// poi fuses cross term: second MMA chain with (P2+P3) rows shifted by -1.
// smem: A1 [128][72] f16, A2 [128][72] f16, V [64][72] f16 (static 46 KB).
// ---------------------------------------------------------------------------
__global__ __launch_bounds__(256) void pv_kernel(
    const float* __restrict__ pvv, const float* __restrict__ tvv,
    const float* __restrict__ dvv, float* __restrict__ out)
{
    __shared__ __align__(16) __half A1s[128][72];
    __shared__ __align__(16) __half A2s[128][72];
    __shared__ __align__(16) __half Vss[64][72];

    const int tid = threadIdx.x, lid = tid & 31, wid = tid >> 5;
    const int z = blockIdx.z, jt = z >> 4, bh = z & 15;
    const int m0 = blockIdx.x * 128;

    const float *P1, *P2 = nullptr, *P3 = nullptr, *Vg;
    float* O;
    int Sq, SkP, Sv;
    if (jt == 0) {
        P1 = out + O_A1 + (size_t)bh * S_ * S_;
        P2 = out + O_A2 + (size_t)bh * SM_ * SM_;
        P3 = out + O_A3 + (size_t)bh * SM_ * SM_;
        Vg = pvv + (size_t)bh * S_ * 64;
        O  = out + O_POI + (size_t)bh * S_ * 64;
        Sq = S_; SkP = S_; Sv = S_;
    } else if (jt == 1) {
        P1 = out + O_A2 + (size_t)bh * SM_ * SM_;
        Vg = tvv + (size_t)bh * SM_ * 64;
        O  = out + O_TIME + (size_t)bh * SM_ * 64;
        Sq = SM_; SkP = SM_; Sv = SM_;
    } else {
        P1 = out + O_A3 + (size_t)bh * SM_ * SM_;
        Vg = dvv + (size_t)bh * SM_ * 64;
        O  = out + O_DIST + (size_t)bh * SM_ * 64;
        Sq = SM_; SkP = SM_; Sv = SM_;
    }

    const uint32_t uA1 = smem_u32(A1s), uA2 = smem_u32(A2s), uV = smem_u32(Vss);
    const int wm = wid & 3, wn = wid >> 2;   // 4x2 warps: 32m x 32n each

    float acc[8][4];
    #pragma unroll
    for (int t = 0; t < 8; ++t)
        #pragma unroll
        for (int j = 0; j < 4; ++j) acc[t][j] = 0.f;

    for (int ck = 0; ck < 2048; ck += 64) {
        // P1 tile -> A1s
        #pragma unroll
        for (int it = 0; it < 16; ++it) {
            int i = it * 256 + tid;               // 4096 slots
            int col = (i & 31) * 2, row = i >> 5;
            int gr = m0 + row, gk = ck + col;
            float p0 = 0.f, p1 = 0.f;
            if (gr < Sq) {
                const float* pr = P1 + (size_t)gr * SkP;
                if (gk < SkP)     p0 = pr[gk];
                if (gk + 1 < SkP) p1 = pr[gk + 1];
            }
            *(uint32_t*)&A1s[row][col] = ph2(p0, p1);
        }
        // cross tile -> A2s (poi only)
        if (jt == 0) {
            #pragma unroll
            for (int it = 0; it < 16; ++it) {
                int i = it * 256 + tid;
                int col = (i & 31) * 2, row = i >> 5;
                int gr = m0 + row - 1, gk = ck + col;
                float p0 = 0.f, p1 = 0.f;
                if (gr >= 0) {
                    size_t base = (size_t)gr * SM_;
                    if (gk < SM_)     p0 = P2[base + gk]     + P3[base + gk];
                    if (gk + 1 < SM_) p1 = P2[base + gk + 1] + P3[base + gk + 1];
                }
                *(uint32_t*)&A2s[row][col] = ph2(p0, p1);
            }
        }
        // V tile -> Vss
        #pragma unroll
        for (int it = 0; it < 8; ++it) {
            int i = it * 256 + tid;               // 2048 slots
            int col = (i & 31) * 2, row = i >> 5;
            int gk = ck + row;
            float v0 = 0.f, v1 = 0.f;
            if (gk < Sv) {
                const float* vr = Vg + (size_t)gk * 64;
                v0 = vr[col]; v1 = vr[col + 1];
            }
            *(uint32_t*)&Vss[row][col] = ph2(v0, v1);
        }
        __syncthreads();

        #pragma unroll
        for (int ks = 0; ks < 4; ++ks) {
            uint32_t b[4][2];
            #pragma unroll
            for (int nb2 = 0; nb2 < 2; ++nb2) {
                int krow = ks * 16 + (((lid >> 3) & 1) << 3) + (lid & 7);
                int ncol = wn * 32 + nb2 * 16 + ((lid >> 4) << 3);
                uint32_t r4[4];
                ldm4t(r4, uV + krow * 144 + ncol * 2);
                b[nb2 * 2][0] = r4[0]; b[nb2 * 2][1] = r4[1];
                b[nb2 * 2 + 1][0] = r4[2]; b[nb2 * 2 + 1][1] = r4[3];
            }
            uint32_t a[2][4];
            #pragma unroll
            for (int mi = 0; mi < 2; ++mi) {
                int row = wm * 32 + mi * 16 + (lid & 15);
                ldm4(a[mi], uA1 + row * 144 + ks * 32 + ((lid >> 4) << 4));
            }
            #pragma unroll
            for (int mi = 0; mi < 2; ++mi)
                #pragma unroll
                for (int nj = 0; nj < 4; ++nj)
                    mma_f16(acc[mi * 4 + nj], a[mi], b[nj]);
            if (jt == 0) {
                #pragma unroll
                for (int mi = 0; mi < 2; ++mi) {
                    int row = wm * 32 + mi * 16 + (lid & 15);
                    ldm4(a[mi], uA2 + row * 144 + ks * 32 + ((lid >> 4) << 4));
                }
                #pragma unroll
                for (int mi = 0; mi < 2; ++mi)
                    #pragma unroll
                    for (int nj = 0; nj < 4; ++nj)
                        mma_f16(acc[mi * 4 + nj], a[mi], b[nj]);
            }
        }
        __syncthreads();
    }

    const int lrow = lid >> 2, lcol = (lid & 3) * 2;
    #pragma unroll
    for (int mi = 0; mi < 2; ++mi) {
        #pragma unroll
        for (int h = 0; h < 2; ++h) {
            int r = m0 + wm * 32 + mi * 16 + h * 8 + lrow;
            if (r >= Sq) continue;
            float* orow = O + (size_t)r * 64;
            #pragma unroll
            for (int nj = 0; nj < 4; ++nj) {
                int cg = wn * 32 + nj * 8 + lcol;
                *(float2*)(orow + cg) =
                    make_float2(acc[mi * 4 + nj][h * 2], acc[mi * 4 + nj][h * 2 + 1]);
            }
        }
    }
}

// ---------------------------------------------------------------------------
extern "C" void kernel_launch(void* const* d_in, const int* in_sizes, int n_in,
                              void* d_out, int out_size)
{
    const float* pq  = (const float*)d_in[0];
    const float* pk  = (const float*)d_in[1];
    const float* pvv = (const float*)d_in[2];
    const float* tq  = (const float*)d_in[3];
    const float* tk  = (const float*)d_in[4];
    const float* tvv = (const float*)d_in[5];
    const float* dq  = (const float*)d_in[6];
    const float* dk  = (const float*)d_in[7];
    const float* dvv = (const float*)d_in[8];
    const int*   msk = (const int*)d_in[9];
    float* out = (float*)d_out;

    static bool attr_done = false;
    if (!attr_done) {
        cudaFuncSetAttribute(qk_kernel, cudaFuncAttributeMaxDynamicSharedMemorySize, 102400);
        attr_done = true;
    }

    qk_kernel<<<dim3(16, 16, 48), 256, 102400>>>(pq, pk, tq, tk, dq, dk, msk, out);
    softmax_kernel<<<dim3(2048, 48), 256>>>(out);
    pv_kernel<<<dim3(16, 1, 48), 256>>>(pvv, tvv, dvv, out);
}

// round 8
// speedup vs baseline: 4.6234x; 2.3804x over previous
#include <cuda_runtime.h>
#include <cuda_bf16.h>
#include <cuda_fp16.h>
#include <cstdint>

#define S_   2048
#define SM_  2047
#define NEGV (-1e9f)

// Output layout (floats): poi, time, dist, attn1, attn2, attn3
#define O_POI   ((size_t)0)
#define O_TIME  ((size_t)2097152)
#define O_DIST  ((size_t)4193280)
#define O_A1    ((size_t)6289408)
#define O_A2    ((size_t)73398272)
#define O_A3    ((size_t)140441616)

// fp16 softmax scratch: [z = stream*16+bh][2048 rows][2048 cols], zero padded
__device__ __align__(16) __half g_p[(size_t)3 * 16 * 2048 * 2048];

// ---------------- warp-MMA helpers ----------------
__device__ __forceinline__ uint32_t smem_u32(const void* p) {
    uint32_t a;
    asm("{ .reg .u64 t; cvta.to.shared.u64 t, %1; cvt.u32.u64 %0, t; }" : "=r"(a) : "l"(p));
    return a;
}
__device__ __forceinline__ void ldm4(uint32_t* r, uint32_t addr) {
    asm volatile("ldmatrix.sync.aligned.m8n8.x4.shared.b16 {%0,%1,%2,%3}, [%4];"
                 : "=r"(r[0]), "=r"(r[1]), "=r"(r[2]), "=r"(r[3]) : "r"(addr));
}
__device__ __forceinline__ void ldm4t(uint32_t* r, uint32_t addr) {
    asm volatile("ldmatrix.sync.aligned.m8n8.x4.trans.shared.b16 {%0,%1,%2,%3}, [%4];"
                 : "=r"(r[0]), "=r"(r[1]), "=r"(r[2]), "=r"(r[3]) : "r"(addr));
}
__device__ __forceinline__ void mma_bf16(float* c, const uint32_t* a, const uint32_t* b) {
    asm volatile("mma.sync.aligned.m16n8k16.row.col.f32.bf16.bf16.f32 "
                 "{%0,%1,%2,%3}, {%4,%5,%6,%7}, {%8,%9}, {%0,%1,%2,%3};"
                 : "+f"(c[0]), "+f"(c[1]), "+f"(c[2]), "+f"(c[3])
                 : "r"(a[0]), "r"(a[1]), "r"(a[2]), "r"(a[3]), "r"(b[0]), "r"(b[1]));
}
__device__ __forceinline__ void mma_f16(float* c, const uint32_t* a, const uint32_t* b) {
    asm volatile("mma.sync.aligned.m16n8k16.row.col.f32.f16.f16.f32 "
                 "{%0,%1,%2,%3}, {%4,%5,%6,%7}, {%8,%9}, {%0,%1,%2,%3};"
                 : "+f"(c[0]), "+f"(c[1]), "+f"(c[2]), "+f"(c[3])
                 : "r"(a[0]), "r"(a[1]), "r"(a[2]), "r"(a[3]), "r"(b[0]), "r"(b[1]));
}
__device__ __forceinline__ void split2(float a, float b, uint32_t& hi, uint32_t& lo) {
    __nv_bfloat16 ha = __float2bfloat16(a), hb = __float2bfloat16(b);
    float la = a - __bfloat162float(ha), lb = b - __bfloat162float(hb);
    __nv_bfloat162 hh; hh.x = ha; hh.y = hb;
    hi = *reinterpret_cast<uint32_t*>(&hh);
    __nv_bfloat162 ll = __floats2bfloat162_rn(la, lb);
    lo = *reinterpret_cast<uint32_t*>(&ll);
}
__device__ __forceinline__ uint32_t ph2(float a, float b) {
    __half2 h = __floats2half2_rn(a, b);
    return *reinterpret_cast<uint32_t*>(&h);
}

// ---------------------------------------------------------------------------
// K1: logits via bf16 3-term split mma.sync, tile 128x128.
// smem rows 272B: A row = [qh(64) | ql(64)], B row = [kh(64) | kl(64)].
// Three MMA chains: qh*kh, qh*kl, ql*kh.
// ---------------------------------------------------------------------------
__global__ __launch_bounds__(256) void qk_kernel(
    const float* __restrict__ pq, const float* __restrict__ pk,
    const float* __restrict__ tq, const float* __restrict__ tk,
    const float* __restrict__ dq, const float* __restrict__ dk,
    const int* __restrict__ mask, float* __restrict__ out)
{
    extern __shared__ __align__(16) char smc[];
    const uint32_t sb = smem_u32(smc);
    const uint32_t sbB = sb + 34816;

    const int tid = threadIdx.x, lid = tid & 31, wid = tid >> 5;
    const int z = blockIdx.z, s = z >> 4, bh = z & 15;
    const int Sq = s ? SM_ : S_, Sk = Sq;
    const int m0 = blockIdx.y * 128, n0 = blockIdx.x * 128;

    const float* Qg = ((s == 0) ? pq : (s == 1) ? tq : dq) + (size_t)bh * Sq * 64;
    const float* Kg = ((s == 0) ? pk : (s == 1) ? tk : dk) + (size_t)bh * Sq * 64;
    float* Aout = (s == 0) ? out + O_A1 + (size_t)bh * S_ * S_
                : (s == 1) ? out + O_A2 + (size_t)bh * SM_ * SM_
                           : out + O_A3 + (size_t)bh * SM_ * SM_;
    const int* M = (s == 0) ? mask + (size_t)(bh >> 3) * S_ * S_ : nullptr;

    #pragma unroll
    for (int it = 0; it < 8; ++it) {
        int i = it * 256 + tid;
        int row = i >> 4, c4 = (i & 15) << 2;
        float4 qv = make_float4(0.f, 0.f, 0.f, 0.f);
        float4 kv = make_float4(0.f, 0.f, 0.f, 0.f);
        if (m0 + row < Sq) qv = *(const float4*)(Qg + (size_t)(m0 + row) * 64 + c4);
        if (n0 + row < Sk) kv = *(const float4*)(Kg + (size_t)(n0 + row) * 64 + c4);
        qv.x *= 0.125f; qv.y *= 0.125f; qv.z *= 0.125f; qv.w *= 0.125f;
        uint32_t h01, h23, l01, l23;
        uint32_t off = (uint32_t)(row * 272 + c4 * 2);
        split2(qv.x, qv.y, h01, l01); split2(qv.z, qv.w, h23, l23);
        *(uint2*)(smc + off)       = make_uint2(h01, h23);
        *(uint2*)(smc + off + 128) = make_uint2(l01, l23);
        split2(kv.x, kv.y, h01, l01); split2(kv.z, kv.w, h23, l23);
        char* bB = smc + 34816;
        *(uint2*)(bB + off)       = make_uint2(h01, h23);
        *(uint2*)(bB + off + 128) = make_uint2(l01, l23);
    }
    __syncthreads();

    const int wm = wid & 3, wn = wid >> 2;
    float acc[16][4];
    #pragma unroll
    for (int t = 0; t < 16; ++t)
        #pragma unroll
        for (int j = 0; j < 4; ++j) acc[t][j] = 0.f;

    #pragma unroll
    for (int term = 0; term < 3; ++term) {
        const uint32_t aoff = (term == 2) ? 128u : 0u;
        const uint32_t boff = (term == 1) ? 128u : 0u;
        #pragma unroll
        for (int ks = 0; ks < 4; ++ks) {
            uint32_t a[2][4];
            #pragma unroll
            for (int mi = 0; mi < 2; ++mi) {
                int row = wm * 32 + mi * 16 + (lid & 15);
                ldm4(a[mi], sb + row * 272 + aoff + ks * 32 + ((lid >> 4) << 4));
            }
            uint32_t b[8][2];
            #pragma unroll
            for (int nb2 = 0; nb2 < 4; ++nb2) {
                int row = wn * 64 + nb2 * 16 + ((lid >> 4) << 3) + (lid & 7);
                uint32_t r4[4];
                ldm4(r4, sbB + row * 272 + boff + ks * 32 + (((lid >> 3) & 1) << 4));
                b[nb2 * 2][0] = r4[0]; b[nb2 * 2][1] = r4[1];
                b[nb2 * 2 + 1][0] = r4[2]; b[nb2 * 2 + 1][1] = r4[3];
            }
            #pragma unroll
            for (int mi = 0; mi < 2; ++mi)
                #pragma unroll
                for (int nj = 0; nj < 8; ++nj)
                    mma_bf16(acc[mi * 8 + nj], a[mi], b[nj]);
        }
    }

    const int lrow = lid >> 2, lcol = (lid & 3) * 2;
    #pragma unroll
    for (int mi = 0; mi < 2; ++mi) {
        #pragma unroll
        for (int h = 0; h < 2; ++h) {
            int q = m0 + wm * 32 + mi * 16 + h * 8 + lrow;
            if (q >= Sq) continue;
            float* orow = Aout + (size_t)q * Sk;
            if (M) {
                const int* Mrow = M + (size_t)q * S_;
                #pragma unroll
                for (int nj = 0; nj < 8; ++nj) {
                    int cg = n0 + wn * 64 + nj * 8 + lcol;
                    int2 mv = *(const int2*)(Mrow + cg);
                    float2 f;
                    f.x = mv.x ? acc[mi * 8 + nj][h * 2]     : NEGV;
                    f.y = mv.y ? acc[mi * 8 + nj][h * 2 + 1] : NEGV;
                    *(float2*)(orow + cg) = f;
                }
            } else {
                #pragma unroll
                for (int nj = 0; nj < 8; ++nj) {
                    int cg = n0 + wn * 64 + nj * 8 + lcol;
                    if (cg < Sk)     orow[cg]     = acc[mi * 8 + nj][h * 2];
                    if (cg + 1 < Sk) orow[cg + 1] = acc[mi * 8 + nj][h * 2 + 1];
                }
            }
        }
    }
}

// ---------------------------------------------------------------------------
// K2: row softmax in place + emit fp16 copy into padded scratch g_p.
// Interleaved access (i = u*256 + tid): fully coalesced, scalar (stride-2047
// rows are only 4B aligned, so no vector ops on the fp32 buffers).
// fp16 stores: 2B scalars, warp-contiguous -> full sectors.
// ---------------------------------------------------------------------------
__global__ __launch_bounds__(256) void softmax_kernel(float* __restrict__ out)
{
    const int row = blockIdx.x, z = blockIdx.y, stream = z >> 4, bh = z & 15;
    int Sk; float* A;
    if (stream == 0)      { Sk = S_;  A = out + O_A1 + (size_t)bh * S_  * S_;  }
    else if (stream == 1) { Sk = SM_; A = out + O_A2 + (size_t)bh * SM_ * SM_; }
    else                  { Sk = SM_; A = out + O_A3 + (size_t)bh * SM_ * SM_; }

    const int tid = threadIdx.x;
    __half* r16 = g_p + ((size_t)z << 22) + ((size_t)row << 11);

    if (row >= Sk) {                 // pad row (row 2047 of streams 1,2)
        ((uint4*)r16)[tid] = make_uint4(0, 0, 0, 0);
        return;
    }

    const float* r = A + (size_t)row * Sk;
    float v[8];
    #pragma unroll
    for (int u = 0; u < 8; ++u) {
        int i = u * 256 + tid;
        v[u] = (i < Sk) ? r[i] : -3.0e38f;
    }

    float m = v[0];
    #pragma unroll
    for (int u = 1; u < 8; ++u) m = fmaxf(m, v[u]);
    #pragma unroll
    for (int o = 16; o > 0; o >>= 1) m = fmaxf(m, __shfl_xor_sync(0xffffffffu, m, o));
    __shared__ float smr[8];
    const int w = tid >> 5, l = tid & 31;
    if (l == 0) smr[w] = m;
    __syncthreads();
    if (tid < 32) {
        float t = (tid < 8) ? smr[tid] : -3.0e38f;
        #pragma unroll
        for (int o = 4; o > 0; o >>= 1) t = fmaxf(t, __shfl_xor_sync(0xffffffffu, t, o));
        if (tid == 0) smr[0] = t;
    }
    __syncthreads();
    m = smr[0];
    __syncthreads();
    float sacc = 0.f;
    #pragma unroll
    for (int u = 0; u < 8; ++u) { v[u] = __expf(v[u] - m); sacc += v[u]; }
    #pragma unroll
    for (int o = 16; o > 0; o >>= 1) sacc += __shfl_xor_sync(0xffffffffu, sacc, o);
    if (l == 0) smr[w] = sacc;
    __syncthreads();
    if (tid < 32) {
        float t = (tid < 8) ? smr[tid] : 0.f;
        #pragma unroll
        for (int o = 4; o > 0; o >>= 1) t += __shfl_xor_sync(0xffffffffu, t, o);
        if (tid == 0) smr[0] = t;
    }
    __syncthreads();
    const float inv = 1.0f / smr[0];

    #pragma unroll
    for (int u = 0; u < 8; ++u) {
        int i = u * 256 + tid;
        float pv = v[u] * inv;             // pad lanes: 0
        r16[i] = __float2half_rn(pv);      // full 2048 cols (pad cols i>=Sk are 0)
        if (i < Sk) ((float*)r)[i] = pv;
    }
}

// ---------------------------------------------------------------------------
// K3: O = P @ V via fp16 mma.sync; P read as fp16 uint4 from g_p (no converts,
// no bounds checks). poi fuses cross term with rows shifted by -1.
// ---------------------------------------------------------------------------
__global__ __launch_bounds__(256) void pv_kernel(
    const float* __restrict__ pvv, const float* __restrict__ tvv,
    const float* __restrict__ dvv, float* __restrict__ out)
{
    __shared__ __align__(16) __half A1s[128][72];
    __shared__ __align__(16) __half A2s[128][72];
    __shared__ __align__(16) __half Vss[64][72];

    const int tid = threadIdx.x, lid = tid & 31, wid = tid >> 5;
    const int z = blockIdx.z, jt = z >> 4, bh = z & 15;
    const int m0 = blockIdx.x * 128;

    const __half* P1h = g_p + ((size_t)(jt * 16 + bh) << 22);
    const __half* P2h = g_p + ((size_t)(16 + bh) << 22);
    const __half* P3h = g_p + ((size_t)(32 + bh) << 22);

    const float* Vg;
    float* O;
    int Sq, Sv;
    if (jt == 0) {
        Vg = pvv + (size_t)bh * S_ * 64;
        O  = out + O_POI + (size_t)bh * S_ * 64;
        Sq = S_; Sv = S_;
    } else if (jt == 1) {
        Vg = tvv + (size_t)bh * SM_ * 64;
        O  = out + O_TIME + (size_t)bh * SM_ * 64;
        Sq = SM_; Sv = SM_;
    } else {
        Vg = dvv + (size_t)bh * SM_ * 64;
        O  = out + O_DIST + (size_t)bh * SM_ * 64;
        Sq = SM_; Sv = SM_;
    }

    const uint32_t uA1 = smem_u32(A1s), uA2 = smem_u32(A2s), uV = smem_u32(Vss);
    const int wm = wid & 3, wn = wid >> 2;

    float acc[8][4];
    #pragma unroll
    for (int t = 0; t < 8; ++t)
        #pragma unroll
        for (int j = 0; j < 4; ++j) acc[t][j] = 0.f;

    for (int ck = 0; ck < 2048; ck += 64) {
        #pragma unroll
        for (int it = 0; it < 4; ++it) {
            int i = it * 256 + tid;
            int row = i >> 3, col8 = (i & 7) << 3;
            *(uint4*)&A1s[row][col8] =
                *(const uint4*)(P1h + (((size_t)(m0 + row)) << 11) + ck + col8);
        }
        if (jt == 0) {
            #pragma unroll
            for (int it = 0; it < 4; ++it) {
                int i = it * 256 + tid;
                int row = i >> 3, col8 = (i & 7) << 3;
                uint4 res = make_uint4(0, 0, 0, 0);
                if (m0 + row > 0) {
                    size_t off = (((size_t)(m0 + row - 1)) << 11) + ck + col8;
                    uint4 a = *(const uint4*)(P2h + off);
                    uint4 b = *(const uint4*)(P3h + off);
                    __half2* ah = (__half2*)&a; __half2* bh2 = (__half2*)&b;
                    __half2* rh = (__half2*)&res;
                    #pragma unroll
                    for (int j = 0; j < 4; ++j) rh[j] = __hadd2(ah[j], bh2[j]);
                }
                *(uint4*)&A2s[row][col8] = res;
            }
        }
        #pragma unroll
        for (int it = 0; it < 8; ++it) {
            int i = it * 256 + tid;
            int col = (i & 31) * 2, row = i >> 5;
            int gk = ck + row;
            float2 vv = make_float2(0.f, 0.f);
            if (gk < Sv) vv = *(const float2*)(Vg + (size_t)gk * 64 + col);
            *(uint32_t*)&Vss[row][col] = ph2(vv.x, vv.y);
        }
        __syncthreads();

        #pragma unroll
        for (int ks = 0; ks < 4; ++ks) {
            uint32_t b[4][2];
            #pragma unroll
            for (int nb2 = 0; nb2 < 2; ++nb2) {
                int krow = ks * 16 + (((lid >> 3) & 1) << 3) + (lid & 7);
                int ncol = wn * 32 + nb2 * 16 + ((lid >> 4) << 3);
                uint32_t r4[4];
                ldm4t(r4, uV + krow * 144 + ncol * 2);
                b[nb2 * 2][0] = r4[0]; b[nb2 * 2][1] = r4[1];
                b[nb2 * 2 + 1][0] = r4[2]; b[nb2 * 2 + 1][1] = r4[3];
            }
            uint32_t a[2][4];
            #pragma unroll
            for (int mi = 0; mi < 2; ++mi) {
                int row = wm * 32 + mi * 16 + (lid & 15);
                ldm4(a[mi], uA1 + row * 144 + ks * 32 + ((lid >> 4) << 4));
            }
            #pragma unroll
            for (int mi = 0; mi < 2; ++mi)
                #pragma unroll
                for (int nj = 0; nj < 4; ++nj)
                    mma_f16(acc[mi * 4 + nj], a[mi], b[nj]);
            if (jt == 0) {
                #pragma unroll
                for (int mi = 0; mi < 2; ++mi) {
                    int row = wm * 32 + mi * 16 + (lid & 15);
                    ldm4(a[mi], uA2 + row * 144 + ks * 32 + ((lid >> 4) << 4));
                }
                #pragma unroll
                for (int mi = 0; mi < 2; ++mi)
                    #pragma unroll
                    for (int nj = 0; nj < 4; ++nj)
                        mma_f16(acc[mi * 4 + nj], a[mi], b[nj]);
            }
        }
        __syncthreads();
    }

    const int lrow = lid >> 2, lcol = (lid & 3) * 2;
    #pragma unroll
    for (int mi = 0; mi < 2; ++mi) {
        #pragma unroll
        for (int h = 0; h < 2; ++h) {
            int r = m0 + wm * 32 + mi * 16 + h * 8 + lrow;
            if (r >= Sq) continue;
            float* orow = O + (size_t)r * 64;
            #pragma unroll
            for (int nj = 0; nj < 4; ++nj) {
                int cg = wn * 32 + nj * 8 + lcol;
                *(float2*)(orow + cg) =
                    make_float2(acc[mi * 4 + nj][h * 2], acc[mi * 4 + nj][h * 2 + 1]);
            }
        }
    }
}

// ---------------------------------------------------------------------------
extern "C" void kernel_launch(void* const* d_in, const int* in_sizes, int n_in,
                              void* d_out, int out_size)
{
    const float* pq  = (const float*)d_in[0];
    const float* pk  = (const float*)d_in[1];
    const float* pvv = (const float*)d_in[2];
    const float* tq  = (const float*)d_in[3];
    const float* tk  = (const float*)d_in[4];
    const float* tvv = (const float*)d_in[5];
    const float* dq  = (const float*)d_in[6];
    const float* dk  = (const float*)d_in[7];
    const float* dvv = (const float*)d_in[8];
    const int*   msk = (const int*)d_in[9];
    float* out = (float*)d_out;

    cudaFuncSetAttribute(qk_kernel, cudaFuncAttributeMaxDynamicSharedMemorySize, 69632);

    qk_kernel<<<dim3(16, 16, 48), 256, 69632>>>(pq, pk, tq, tk, dq, dk, msk, out);
    softmax_kernel<<<dim3(2048, 48), 256>>>(out);
    pv_kernel<<<dim3(16, 1, 48), 256>>>(pvv, tvv, dvv, out);
}

// round 9
// speedup vs baseline: 5.2003x; 1.1248x over previous
#include <cuda_runtime.h>
#include <cuda_bf16.h>
#include <cuda_fp16.h>
#include <cstdint>

#define S_   2048
#define SM_  2047
#define NEGV (-1e9f)

// Output layout (floats): poi, time, dist, attn1, attn2, attn3
#define O_POI   ((size_t)0)
#define O_TIME  ((size_t)2097152)
#define O_DIST  ((size_t)4193280)
#define O_A1    ((size_t)6289408)
#define O_A2    ((size_t)73398272)
#define O_A3    ((size_t)140441616)

// fp16 softmax scratch: [z = stream*16+bh][2048 rows][2048 cols], zero padded
__device__ __align__(16) __half g_p[(size_t)3 * 16 * 2048 * 2048];

// ---------------- warp-MMA helpers ----------------
__device__ __forceinline__ uint32_t smem_u32(const void* p) {
    uint32_t a;
    asm("{ .reg .u64 t; cvta.to.shared.u64 t, %1; cvt.u32.u64 %0, t; }" : "=r"(a) : "l"(p));
    return a;
}
__device__ __forceinline__ void ldm4(uint32_t* r, uint32_t addr) {
    asm volatile("ldmatrix.sync.aligned.m8n8.x4.shared.b16 {%0,%1,%2,%3}, [%4];"
                 : "=r"(r[0]), "=r"(r[1]), "=r"(r[2]), "=r"(r[3]) : "r"(addr));
}
__device__ __forceinline__ void ldm4t(uint32_t* r, uint32_t addr) {
    asm volatile("ldmatrix.sync.aligned.m8n8.x4.trans.shared.b16 {%0,%1,%2,%3}, [%4];"
                 : "=r"(r[0]), "=r"(r[1]), "=r"(r[2]), "=r"(r[3]) : "r"(addr));
}
__device__ __forceinline__ void mma_bf16(float* c, const uint32_t* a, const uint32_t* b) {
    asm volatile("mma.sync.aligned.m16n8k16.row.col.f32.bf16.bf16.f32 "
                 "{%0,%1,%2,%3}, {%4,%5,%6,%7}, {%8,%9}, {%0,%1,%2,%3};"
                 : "+f"(c[0]), "+f"(c[1]), "+f"(c[2]), "+f"(c[3])
                 : "r"(a[0]), "r"(a[1]), "r"(a[2]), "r"(a[3]), "r"(b[0]), "r"(b[1]));
}
__device__ __forceinline__ void mma_f16(float* c, const uint32_t* a, const uint32_t* b) {
    asm volatile("mma.sync.aligned.m16n8k16.row.col.f32.f16.f16.f32 "
                 "{%0,%1,%2,%3}, {%4,%5,%6,%7}, {%8,%9}, {%0,%1,%2,%3};"
                 : "+f"(c[0]), "+f"(c[1]), "+f"(c[2]), "+f"(c[3])
                 : "r"(a[0]), "r"(a[1]), "r"(a[2]), "r"(a[3]), "r"(b[0]), "r"(b[1]));
}
__device__ __forceinline__ void split2(float a, float b, uint32_t& hi, uint32_t& lo) {
    __nv_bfloat16 ha = __float2bfloat16(a), hb = __float2bfloat16(b);
    float la = a - __bfloat162float(ha), lb = b - __bfloat162float(hb);
    __nv_bfloat162 hh; hh.x = ha; hh.y = hb;
    hi = *reinterpret_cast<uint32_t*>(&hh);
    __nv_bfloat162 ll = __floats2bfloat162_rn(la, lb);
    lo = *reinterpret_cast<uint32_t*>(&ll);
}
__device__ __forceinline__ uint32_t ph2(float a, float b) {
    __half2 h = __floats2half2_rn(a, b);
    return *reinterpret_cast<uint32_t*>(&h);
}

// ---------------------------------------------------------------------------
// K1: logits via bf16 3-term split mma.sync, tile 128x128.
// smem rows 272B: A row = [qh(64) | ql(64)], B row = [kh(64) | kl(64)].
// Three MMA chains: qh*kh, qh*kl, ql*kh.
// __launch_bounds__(256, 2): cap regs at 128 so 2 blocks/SM stay resident.
// ---------------------------------------------------------------------------
__global__ __launch_bounds__(256, 2) void qk_kernel(
    const float* __restrict__ pq, const float* __restrict__ pk,
    const float* __restrict__ tq, const float* __restrict__ tk,
    const float* __restrict__ dq, const float* __restrict__ dk,
    const int* __restrict__ mask, float* __restrict__ out)
{
    extern __shared__ __align__(16) char smc[];
    const uint32_t sb = smem_u32(smc);
    const uint32_t sbB = sb + 34816;

    const int tid = threadIdx.x, lid = tid & 31, wid = tid >> 5;
    const int z = blockIdx.z, s = z >> 4, bh = z & 15;
    const int Sq = s ? SM_ : S_, Sk = Sq;
    const int m0 = blockIdx.y * 128, n0 = blockIdx.x * 128;

    const float* Qg = ((s == 0) ? pq : (s == 1) ? tq : dq) + (size_t)bh * Sq * 64;
    const float* Kg = ((s == 0) ? pk : (s == 1) ? tk : dk) + (size_t)bh * Sq * 64;
    float* Aout = (s == 0) ? out + O_A1 + (size_t)bh * S_ * S_
                : (s == 1) ? out + O_A2 + (size_t)bh * SM_ * SM_
                           : out + O_A3 + (size_t)bh * SM_ * SM_;
    const int* M = (s == 0) ? mask + (size_t)(bh >> 3) * S_ * S_ : nullptr;

    #pragma unroll
    for (int it = 0; it < 8; ++it) {
        int i = it * 256 + tid;
        int row = i >> 4, c4 = (i & 15) << 2;
        float4 qv = make_float4(0.f, 0.f, 0.f, 0.f);
        float4 kv = make_float4(0.f, 0.f, 0.f, 0.f);
        if (m0 + row < Sq) qv = *(const float4*)(Qg + (size_t)(m0 + row) * 64 + c4);
        if (n0 + row < Sk) kv = *(const float4*)(Kg + (size_t)(n0 + row) * 64 + c4);
        qv.x *= 0.125f; qv.y *= 0.125f; qv.z *= 0.125f; qv.w *= 0.125f;
        uint32_t h01, h23, l01, l23;
        uint32_t off = (uint32_t)(row * 272 + c4 * 2);
        split2(qv.x, qv.y, h01, l01); split2(qv.z, qv.w, h23, l23);
        *(uint2*)(smc + off)       = make_uint2(h01, h23);
        *(uint2*)(smc + off + 128) = make_uint2(l01, l23);
        split2(kv.x, kv.y, h01, l01); split2(kv.z, kv.w, h23, l23);
        char* bB = smc + 34816;
        *(uint2*)(bB + off)       = make_uint2(h01, h23);
        *(uint2*)(bB + off + 128) = make_uint2(l01, l23);
    }
    __syncthreads();

    const int wm = wid & 3, wn = wid >> 2;
    float acc[16][4];
    #pragma unroll
    for (int t = 0; t < 16; ++t)
        #pragma unroll
        for (int j = 0; j < 4; ++j) acc[t][j] = 0.f;

    #pragma unroll
    for (int term = 0; term < 3; ++term) {
        const uint32_t aoff = (term == 2) ? 128u : 0u;
        const uint32_t boff = (term == 1) ? 128u : 0u;
        #pragma unroll
        for (int ks = 0; ks < 4; ++ks) {
            uint32_t a[2][4];
            #pragma unroll
            for (int mi = 0; mi < 2; ++mi) {
                int row = wm * 32 + mi * 16 + (lid & 15);
                ldm4(a[mi], sb + row * 272 + aoff + ks * 32 + ((lid >> 4) << 4));
            }
            uint32_t b[8][2];
            #pragma unroll
            for (int nb2 = 0; nb2 < 4; ++nb2) {
                int row = wn * 64 + nb2 * 16 + ((lid >> 4) << 3) + (lid & 7);
                uint32_t r4[4];
                ldm4(r4, sbB + row * 272 + boff + ks * 32 + (((lid >> 3) & 1) << 4));
                b[nb2 * 2][0] = r4[0]; b[nb2 * 2][1] = r4[1];
                b[nb2 * 2 + 1][0] = r4[2]; b[nb2 * 2 + 1][1] = r4[3];
            }
            #pragma unroll
            for (int mi = 0; mi < 2; ++mi)
                #pragma unroll
                for (int nj = 0; nj < 8; ++nj)
                    mma_bf16(acc[mi * 8 + nj], a[mi], b[nj]);
        }
    }

    const int lrow = lid >> 2, lcol = (lid & 3) * 2;
    #pragma unroll
    for (int mi = 0; mi < 2; ++mi) {
        #pragma unroll
        for (int h = 0; h < 2; ++h) {
            int q = m0 + wm * 32 + mi * 16 + h * 8 + lrow;
            if (q >= Sq) continue;
            float* orow = Aout + (size_t)q * Sk;
            if (M) {
                const int* Mrow = M + (size_t)q * S_;
                #pragma unroll
                for (int nj = 0; nj < 8; ++nj) {
                    int cg = n0 + wn * 64 + nj * 8 + lcol;
                    int2 mv = *(const int2*)(Mrow + cg);
                    float2 f;
                    f.x = mv.x ? acc[mi * 8 + nj][h * 2]     : NEGV;
                    f.y = mv.y ? acc[mi * 8 + nj][h * 2 + 1] : NEGV;
                    *(float2*)(orow + cg) = f;
                }
            } else {
                #pragma unroll
                for (int nj = 0; nj < 8; ++nj) {
                    int cg = n0 + wn * 64 + nj * 8 + lcol;
                    if (cg < Sk)     orow[cg]     = acc[mi * 8 + nj][h * 2];
                    if (cg + 1 < Sk) orow[cg + 1] = acc[mi * 8 + nj][h * 2 + 1];
                }
            }
        }
    }
}

// ---------------------------------------------------------------------------
// K2: row softmax in place + emit fp16 copy into padded scratch g_p.
// ---------------------------------------------------------------------------
__global__ __launch_bounds__(256) void softmax_kernel(float* __restrict__ out)
{
    const int row = blockIdx.x, z = blockIdx.y, stream = z >> 4, bh = z & 15;
    int Sk; float* A;
    if (stream == 0)      { Sk = S_;  A = out + O_A1 + (size_t)bh * S_  * S_;  }
    else if (stream == 1) { Sk = SM_; A = out + O_A2 + (size_t)bh * SM_ * SM_; }
    else                  { Sk = SM_; A = out + O_A3 + (size_t)bh * SM_ * SM_; }

    const int tid = threadIdx.x;
    __half* r16 = g_p + ((size_t)z << 22) + ((size_t)row << 11);

    if (row >= Sk) {                 // pad row (row 2047 of streams 1,2)
        ((uint4*)r16)[tid] = make_uint4(0, 0, 0, 0);
        return;
    }

    const float* r = A + (size_t)row * Sk;
    float v[8];
    #pragma unroll
    for (int u = 0; u < 8; ++u) {
        int i = u * 256 + tid;
        v[u] = (i < Sk) ? r[i] : -3.0e38f;
    }

    float m = v[0];
    #pragma unroll
    for (int u = 1; u < 8; ++u) m = fmaxf(m, v[u]);
    #pragma unroll
    for (int o = 16; o > 0; o >>= 1) m = fmaxf(m, __shfl_xor_sync(0xffffffffu, m, o));
    __shared__ float smr[8];
    const int w = tid >> 5, l = tid & 31;
    if (l == 0) smr[w] = m;
    __syncthreads();
    if (tid < 32) {
        float t = (tid < 8) ? smr[tid] : -3.0e38f;
        #pragma unroll
        for (int o = 4; o > 0; o >>= 1) t = fmaxf(t, __shfl_xor_sync(0xffffffffu, t, o));
        if (tid == 0) smr[0] = t;
    }
    __syncthreads();
    m = smr[0];
    __syncthreads();
    float sacc = 0.f;
    #pragma unroll
    for (int u = 0; u < 8; ++u) { v[u] = __expf(v[u] - m); sacc += v[u]; }
    #pragma unroll
    for (int o = 16; o > 0; o >>= 1) sacc += __shfl_xor_sync(0xffffffffu, sacc, o);
    if (l == 0) smr[w] = sacc;
    __syncthreads();
    if (tid < 32) {
        float t = (tid < 8) ? smr[tid] : 0.f;
        #pragma unroll
        for (int o = 4; o > 0; o >>= 1) t += __shfl_xor_sync(0xffffffffu, t, o);
        if (tid == 0) smr[0] = t;
    }
    __syncthreads();
    const float inv = 1.0f / smr[0];

    #pragma unroll
    for (int u = 0; u < 8; ++u) {
        int i = u * 256 + tid;
        float pv = v[u] * inv;             // pad lanes: 0
        r16[i] = __float2half_rn(pv);      // full 2048 cols (pad cols are 0)
        if (i < Sk) ((float*)r)[i] = pv;
    }
}

// ---------------------------------------------------------------------------
// K3: O = P @ V via fp16 mma.sync; P read as fp16 uint4 from g_p.
// poi fuses cross term with rows shifted by -1.
// ---------------------------------------------------------------------------
__global__ __launch_bounds__(256, 2) void pv_kernel(
    const float* __restrict__ pvv, const float* __restrict__ tvv,
    const float* __restrict__ dvv, float* __restrict__ out)
{
    __shared__ __align__(16) __half A1s[128][72];
    __shared__ __align__(16) __half A2s[128][72];
    __shared__ __align__(16) __half Vss[64][72];

    const int tid = threadIdx.x, lid = tid & 31, wid = tid >> 5;
    const int z = blockIdx.z, jt = z >> 4, bh = z & 15;
    const int m0 = blockIdx.x * 128;

    const __half* P1h = g_p + ((size_t)(jt * 16 + bh) << 22);
    const __half* P2h = g_p + ((size_t)(16 + bh) << 22);
    const __half* P3h = g_p + ((size_t)(32 + bh) << 22);

    const float* Vg;
    float* O;
    int Sq, Sv;
    if (jt == 0) {
        Vg = pvv + (size_t)bh * S_ * 64;
        O  = out + O_POI + (size_t)bh * S_ * 64;
        Sq = S_; Sv = S_;
    } else if (jt == 1) {
        Vg = tvv + (size_t)bh * SM_ * 64;
        O  = out + O_TIME + (size_t)bh * SM_ * 64;
        Sq = SM_; Sv = SM_;
    } else {
        Vg = dvv + (size_t)bh * SM_ * 64;
        O  = out + O_DIST + (size_t)bh * SM_ * 64;
        Sq = SM_; Sv = SM_;
    }

    const uint32_t uA1 = smem_u32(A1s), uA2 = smem_u32(A2s), uV = smem_u32(Vss);
    const int wm = wid & 3, wn = wid >> 2;

    float acc[8][4];
    #pragma unroll
    for (int t = 0; t < 8; ++t)
        #pragma unroll
        for (int j = 0; j < 4; ++j) acc[t][j] = 0.f;

    for (int ck = 0; ck < 2048; ck += 64) {
        #pragma unroll
        for (int it = 0; it < 4; ++it) {
            int i = it * 256 + tid;
            int row = i >> 3, col8 = (i & 7) << 3;
            *(uint4*)&A1s[row][col8] =
                *(const uint4*)(P1h + (((size_t)(m0 + row)) << 11) + ck + col8);
        }
        if (jt == 0) {
            #pragma unroll
            for (int it = 0; it < 4; ++it) {
                int i = it * 256 + tid;
                int row = i >> 3, col8 = (i & 7) << 3;
                uint4 res = make_uint4(0, 0, 0, 0);
                if (m0 + row > 0) {
                    size_t off = (((size_t)(m0 + row - 1)) << 11) + ck + col8;
                    uint4 a = *(const uint4*)(P2h + off);
                    uint4 b = *(const uint4*)(P3h + off);
                    __half2* ah = (__half2*)&a; __half2* bh2 = (__half2*)&b;
                    __half2* rh = (__half2*)&res;
                    #pragma unroll
                    for (int j = 0; j < 4; ++j) rh[j] = __hadd2(ah[j], bh2[j]);
                }
                *(uint4*)&A2s[row][col8] = res;
            }
        }
        #pragma unroll
        for (int it = 0; it < 8; ++it) {
            int i = it * 256 + tid;
            int col = (i & 31) * 2, row = i >> 5;
            int gk = ck + row;
            float2 vv = make_float2(0.f, 0.f);
            if (gk < Sv) vv = *(const float2*)(Vg + (size_t)gk * 64 + col);
            *(uint32_t*)&Vss[row][col] = ph2(vv.x, vv.y);
        }
        __syncthreads();

        #pragma unroll
        for (int ks = 0; ks < 4; ++ks) {
            uint32_t b[4][2];
            #pragma unroll
            for (int nb2 = 0; nb2 < 2; ++nb2) {
                int krow = ks * 16 + (((lid >> 3) & 1) << 3) + (lid & 7);
                int ncol = wn * 32 + nb2 * 16 + ((lid >> 4) << 3);
                uint32_t r4[4];
                ldm4t(r4, uV + krow * 144 + ncol * 2);
                b[nb2 * 2][0] = r4[0]; b[nb2 * 2][1] = r4[1];
                b[nb2 * 2 + 1][0] = r4[2]; b[nb2 * 2 + 1][1] = r4[3];
            }
            uint32_t a[2][4];
            #pragma unroll
            for (int mi = 0; mi < 2; ++mi) {
                int row = wm * 32 + mi * 16 + (lid & 15);
                ldm4(a[mi], uA1 + row * 144 + ks * 32 + ((lid >> 4) << 4));
            }
            #pragma unroll
            for (int mi = 0; mi < 2; ++mi)
                #pragma unroll
                for (int nj = 0; nj < 4; ++nj)
                    mma_f16(acc[mi * 4 + nj], a[mi], b[nj]);
            if (jt == 0) {
                #pragma unroll
                for (int mi = 0; mi < 2; ++mi) {
                    int row = wm * 32 + mi * 16 + (lid & 15);
                    ldm4(a[mi], uA2 + row * 144 + ks * 32 + ((lid >> 4) << 4));
                }
                #pragma unroll
                for (int mi = 0; mi < 2; ++mi)
                    #pragma unroll
                    for (int nj = 0; nj < 4; ++nj)
                        mma_f16(acc[mi * 4 + nj], a[mi], b[nj]);
            }
        }
        __syncthreads();
    }

    const int lrow = lid >> 2, lcol = (lid & 3) * 2;
    #pragma unroll
    for (int mi = 0; mi < 2; ++mi) {
        #pragma unroll
        for (int h = 0; h < 2; ++h) {
            int r = m0 + wm * 32 + mi * 16 + h * 8 + lrow;
            if (r >= Sq) continue;
            float* orow = O + (size_t)r * 64;
            #pragma unroll
            for (int nj = 0; nj < 4; ++nj) {
                int cg = wn * 32 + nj * 8 + lcol;
                *(float2*)(orow + cg) =
                    make_float2(acc[mi * 4 + nj][h * 2], acc[mi * 4 + nj][h * 2 + 1]);
            }
        }
    }
}

// ---------------------------------------------------------------------------
extern "C" void kernel_launch(void* const* d_in, const int* in_sizes, int n_in,
                              void* d_out, int out_size)
{
    const float* pq  = (const float*)d_in[0];
    const float* pk  = (const float*)d_in[1];
    const float* pvv = (const float*)d_in[2];
    const float* tq  = (const float*)d_in[3];
    const float* tk  = (const float*)d_in[4];
    const float* tvv = (const float*)d_in[5];
    const float* dq  = (const float*)d_in[6];
    const float* dk  = (const float*)d_in[7];
    const float* dvv = (const float*)d_in[8];
    const int*   msk = (const int*)d_in[9];
    float* out = (float*)d_out;

    cudaFuncSetAttribute(qk_kernel, cudaFuncAttributeMaxDynamicSharedMemorySize, 69632);

    qk_kernel<<<dim3(16, 16, 48), 256, 69632>>>(pq, pk, tq, tk, dq, dk, msk, out);
    softmax_kernel<<<dim3(2048, 48), 256>>>(out);
    pv_kernel<<<dim3(16, 1, 48), 256>>>(pvv, tvv, dvv, out);
}

// round 10
// speedup vs baseline: 5.6645x; 1.0893x over previous
#include <cuda_runtime.h>
#include <cuda_bf16.h>
#include <cuda_fp16.h>
#include <cstdint>

#define S_   2048
#define SM_  2047
#define NEGV (-1e9f)

// Output layout (floats): poi, time, dist, attn1, attn2, attn3
#define O_POI   ((size_t)0)
#define O_TIME  ((size_t)2097152)
#define O_DIST  ((size_t)4193280)
#define O_A1    ((size_t)6289408)
#define O_A2    ((size_t)73398272)
#define O_A3    ((size_t)140441616)

// fp16 softmax scratch: [z][2048][2048], zero padded
__device__ __align__(16) __half g_p[(size_t)3 * 16 * 2048 * 2048];
// pre-split Q,K: [z][2048 rows][ qh(64) | ql(64) ] bf16, zero padded rows
__device__ __align__(16) __nv_bfloat16 g_q[(size_t)48 * 2048 * 128];
__device__ __align__(16) __nv_bfloat16 g_k[(size_t)48 * 2048 * 128];
// V fp16: [z][2048 rows][64], zero padded rows
__device__ __align__(16) __half g_v[(size_t)48 * 2048 * 64];

// ---------------- helpers ----------------
__device__ __forceinline__ uint32_t smem_u32(const void* p) {
    uint32_t a;
    asm("{ .reg .u64 t; cvta.to.shared.u64 t, %1; cvt.u32.u64 %0, t; }" : "=r"(a) : "l"(p));
    return a;
}
__device__ __forceinline__ void cpa16(uint32_t d, const void* g) {
    asm volatile("cp.async.cg.shared.global [%0], [%1], 16;" :: "r"(d), "l"(g));
}
__device__ __forceinline__ void cpa_wait() {
    asm volatile("cp.async.commit_group;");
    asm volatile("cp.async.wait_group 0;");
}
__device__ __forceinline__ void ldm4(uint32_t* r, uint32_t addr) {
    asm volatile("ldmatrix.sync.aligned.m8n8.x4.shared.b16 {%0,%1,%2,%3}, [%4];"
                 : "=r"(r[0]), "=r"(r[1]), "=r"(r[2]), "=r"(r[3]) : "r"(addr));
}
__device__ __forceinline__ void ldm4t(uint32_t* r, uint32_t addr) {
    asm volatile("ldmatrix.sync.aligned.m8n8.x4.trans.shared.b16 {%0,%1,%2,%3}, [%4];"
                 : "=r"(r[0]), "=r"(r[1]), "=r"(r[2]), "=r"(r[3]) : "r"(addr));
}
__device__ __forceinline__ void mma_bf16(float* c, const uint32_t* a, const uint32_t* b) {
    asm volatile("mma.sync.aligned.m16n8k16.row.col.f32.bf16.bf16.f32 "
                 "{%0,%1,%2,%3}, {%4,%5,%6,%7}, {%8,%9}, {%0,%1,%2,%3};"
                 : "+f"(c[0]), "+f"(c[1]), "+f"(c[2]), "+f"(c[3])
                 : "r"(a[0]), "r"(a[1]), "r"(a[2]), "r"(a[3]), "r"(b[0]), "r"(b[1]));
}
__device__ __forceinline__ void mma_f16(float* c, const uint32_t* a, const uint32_t* b) {
    asm volatile("mma.sync.aligned.m16n8k16.row.col.f32.f16.f16.f32 "
                 "{%0,%1,%2,%3}, {%4,%5,%6,%7}, {%8,%9}, {%0,%1,%2,%3};"
                 : "+f"(c[0]), "+f"(c[1]), "+f"(c[2]), "+f"(c[3])
                 : "r"(a[0]), "r"(a[1]), "r"(a[2]), "r"(a[3]), "r"(b[0]), "r"(b[1]));
}
__device__ __forceinline__ void split2(float a, float b, uint32_t& hi, uint32_t& lo) {
    __nv_bfloat16 ha = __float2bfloat16(a), hb = __float2bfloat16(b);
    float la = a - __bfloat162float(ha), lb = b - __bfloat162float(hb);
    __nv_bfloat162 hh; hh.x = ha; hh.y = hb;
    hi = *reinterpret_cast<uint32_t*>(&hh);
    __nv_bfloat162 ll = __floats2bfloat162_rn(la, lb);
    lo = *reinterpret_cast<uint32_t*>(&ll);
}
__device__ __forceinline__ uint32_t ph2(float a, float b) {
    __half2 h = __floats2half2_rn(a, b);
    return *reinterpret_cast<uint32_t*>(&h);
}

// ---------------------------------------------------------------------------
// K0: one-shot conversion. Q -> (q/8) bf16 hi/lo split, K -> bf16 hi/lo split,
// V -> fp16. Rows >= Sq zero-padded (uniform 2048 stride downstream).
// Thread handles one (z, row, 4-float chunk).
// ---------------------------------------------------------------------------
__global__ __launch_bounds__(256) void convert_kernel(
    const float* __restrict__ pq, const float* __restrict__ pk, const float* __restrict__ pvv,
    const float* __restrict__ tq, const float* __restrict__ tk, const float* __restrict__ tvv,
    const float* __restrict__ dq, const float* __restrict__ dk, const float* __restrict__ dvv)
{
    int gid = blockIdx.x * 256 + threadIdx.x;     // 48*2048*16
    int c4  = gid & 15;
    int row = (gid >> 4) & 2047;
    int z   = gid >> 15;
    int s = z >> 4, bh = z & 15;

    const float *q, *k, *v;
    int Sq;
    if (s == 0)      { q = pq; k = pk; v = pvv; Sq = S_;  }
    else if (s == 1) { q = tq; k = tk; v = tvv; Sq = SM_; }
    else             { q = dq; k = dk; v = dvv; Sq = SM_; }

    float4 qv = make_float4(0.f,0.f,0.f,0.f), kv = qv, vv = qv;
    if (row < Sq) {
        size_t in = ((size_t)bh * Sq + row) * 64 + c4 * 4;
        qv = *(const float4*)(q + in);
        kv = *(const float4*)(k + in);
        vv = *(const float4*)(v + in);
        qv.x *= 0.125f; qv.y *= 0.125f; qv.z *= 0.125f; qv.w *= 0.125f;
    }
    size_t base = ((size_t)z * 2048 + row) * 128 + c4 * 4;
    uint32_t h01, h23, l01, l23;
    split2(qv.x, qv.y, h01, l01); split2(qv.z, qv.w, h23, l23);
    *(uint2*)(g_q + base)      = make_uint2(h01, h23);
    *(uint2*)(g_q + base + 64) = make_uint2(l01, l23);
    split2(kv.x, kv.y, h01, l01); split2(kv.z, kv.w, h23, l23);
    *(uint2*)(g_k + base)      = make_uint2(h01, h23);
    *(uint2*)(g_k + base + 64) = make_uint2(l01, l23);
    *(uint2*)(g_v + ((size_t)z * 2048 + row) * 64 + c4 * 4) =
        make_uint2(ph2(vv.x, vv.y), ph2(vv.z, vv.w));
}

// ---------------------------------------------------------------------------
// K1: logits via bf16 3-term split mma.sync, tile 128x128.
// Staging = pure cp.async 16B copies from pre-split g_q/g_k (zero padded).
// smem rows 272B: [hi(128B) | lo(128B)] + 16B pad.
// ---------------------------------------------------------------------------
__global__ __launch_bounds__(256, 2) void qk_kernel(
    const int* __restrict__ mask, float* __restrict__ out)
{
    extern __shared__ __align__(16) char smc[];
    const uint32_t sb = smem_u32(smc);
    const uint32_t sbB = sb + 34816;

    const int tid = threadIdx.x, lid = tid & 31, wid = tid >> 5;
    const int z = blockIdx.z, s = z >> 4, bh = z & 15;
    const int Sq = s ? SM_ : S_, Sk = Sq;
    const int m0 = blockIdx.y * 128, n0 = blockIdx.x * 128;

    float* Aout = (s == 0) ? out + O_A1 + (size_t)bh * S_ * S_
                : (s == 1) ? out + O_A2 + (size_t)bh * SM_ * SM_
                           : out + O_A3 + (size_t)bh * SM_ * SM_;
    const int* M = (s == 0) ? mask + (size_t)(bh >> 3) * S_ * S_ : nullptr;

    const __nv_bfloat16* Qs = g_q + ((size_t)z * 2048 + m0) * 128;
    const __nv_bfloat16* Ks = g_k + ((size_t)z * 2048 + n0) * 128;

    #pragma unroll
    for (int it = 0; it < 8; ++it) {
        int i = it * 256 + tid;          // 2048: 128 rows x 16 chunks
        int r = i >> 4, c = i & 15;
        cpa16(sb  + r * 272 + c * 16, Qs + (size_t)r * 128 + c * 8);
        cpa16(sbB + r * 272 + c * 16, Ks + (size_t)r * 128 + c * 8);
    }
    cpa_wait();
    __syncthreads();

    const int wm = wid & 3, wn = wid >> 2;
    float acc[16][4];
    #pragma unroll
    for (int t = 0; t < 16; ++t)
        #pragma unroll
        for (int j = 0; j < 4; ++j) acc[t][j] = 0.f;

    #pragma unroll
    for (int term = 0; term < 3; ++term) {
        const uint32_t aoff = (term == 2) ? 128u : 0u;   // ql
        const uint32_t boff = (term == 1) ? 128u : 0u;   // kl
        #pragma unroll
        for (int ks = 0; ks < 4; ++ks) {
            uint32_t a[2][4];
            #pragma unroll
            for (int mi = 0; mi < 2; ++mi) {
                int row = wm * 32 + mi * 16 + (lid & 15);
                ldm4(a[mi], sb + row * 272 + aoff + ks * 32 + ((lid >> 4) << 4));
            }
            uint32_t b[8][2];
            #pragma unroll
            for (int nb2 = 0; nb2 < 4; ++nb2) {
                int row = wn * 64 + nb2 * 16 + ((lid >> 4) << 3) + (lid & 7);
                uint32_t r4[4];
                ldm4(r4, sbB + row * 272 + boff + ks * 32 + (((lid >> 3) & 1) << 4));
                b[nb2 * 2][0] = r4[0]; b[nb2 * 2][1] = r4[1];
                b[nb2 * 2 + 1][0] = r4[2]; b[nb2 * 2 + 1][1] = r4[3];
            }
            #pragma unroll
            for (int mi = 0; mi < 2; ++mi)
                #pragma unroll
                for (int nj = 0; nj < 8; ++nj)
                    mma_bf16(acc[mi * 8 + nj], a[mi], b[nj]);
        }
    }

    const int lrow = lid >> 2, lcol = (lid & 3) * 2;
    #pragma unroll
    for (int mi = 0; mi < 2; ++mi) {
        #pragma unroll
        for (int h = 0; h < 2; ++h) {
            int q = m0 + wm * 32 + mi * 16 + h * 8 + lrow;
            if (q >= Sq) continue;
            float* orow = Aout + (size_t)q * Sk;
            if (M) {
                const int* Mrow = M + (size_t)q * S_;
                #pragma unroll
                for (int nj = 0; nj < 8; ++nj) {
                    int cg = n0 + wn * 64 + nj * 8 + lcol;
                    int2 mv = *(const int2*)(Mrow + cg);
                    float2 f;
                    f.x = mv.x ? acc[mi * 8 + nj][h * 2]     : NEGV;
                    f.y = mv.y ? acc[mi * 8 + nj][h * 2 + 1] : NEGV;
                    *(float2*)(orow + cg) = f;
                }
            } else {
                #pragma unroll
                for (int nj = 0; nj < 8; ++nj) {
                    int cg = n0 + wn * 64 + nj * 8 + lcol;
                    if (cg < Sk)     orow[cg]     = acc[mi * 8 + nj][h * 2];
                    if (cg + 1 < Sk) orow[cg + 1] = acc[mi * 8 + nj][h * 2 + 1];
                }
            }
        }
    }
}

// ---------------------------------------------------------------------------
// K2: row softmax in place + fp16 copy to g_p. Stream 0 (stride 2048, 16B
// aligned) uses float4/uint4 vector path; streams 1,2 (stride 2047) scalar.
// ---------------------------------------------------------------------------
__global__ __launch_bounds__(256) void softmax_kernel(float* __restrict__ out)
{
    const int row = blockIdx.x, z = blockIdx.y, stream = z >> 4, bh = z & 15;
    int Sk; float* A;
    if (stream == 0)      { Sk = S_;  A = out + O_A1 + (size_t)bh * S_  * S_;  }
    else if (stream == 1) { Sk = SM_; A = out + O_A2 + (size_t)bh * SM_ * SM_; }
    else                  { Sk = SM_; A = out + O_A3 + (size_t)bh * SM_ * SM_; }

    const int tid = threadIdx.x;
    __half* r16 = g_p + ((size_t)z << 22) + ((size_t)row << 11);

    if (row >= Sk) {
        ((uint4*)r16)[tid] = make_uint4(0, 0, 0, 0);
        return;
    }

    float* r = A + (size_t)row * Sk;
    const bool vec = (stream == 0);
    const int i0 = tid * 8;
    float v[8];
    if (vec) {
        float4 a = *(const float4*)(r + i0), b = *(const float4*)(r + i0 + 4);
        v[0]=a.x; v[1]=a.y; v[2]=a.z; v[3]=a.w; v[4]=b.x; v[5]=b.y; v[6]=b.z; v[7]=b.w;
    } else {
        #pragma unroll
        for (int u = 0; u < 8; ++u) {
            int i = u * 256 + tid;
            v[u] = (i < Sk) ? r[i] : -3.0e38f;
        }
    }

    float m = v[0];
    #pragma unroll
    for (int u = 1; u < 8; ++u) m = fmaxf(m, v[u]);
    #pragma unroll
    for (int o = 16; o > 0; o >>= 1) m = fmaxf(m, __shfl_xor_sync(0xffffffffu, m, o));
    __shared__ float smr[8];
    const int w = tid >> 5, l = tid & 31;
    if (l == 0) smr[w] = m;
    __syncthreads();
    if (tid < 32) {
        float t = (tid < 8) ? smr[tid] : -3.0e38f;
        #pragma unroll
        for (int o = 4; o > 0; o >>= 1) t = fmaxf(t, __shfl_xor_sync(0xffffffffu, t, o));
        if (tid == 0) smr[0] = t;
    }
    __syncthreads();
    m = smr[0];
    __syncthreads();
    float sacc = 0.f;
    #pragma unroll
    for (int u = 0; u < 8; ++u) { v[u] = __expf(v[u] - m); sacc += v[u]; }
    #pragma unroll
    for (int o = 16; o > 0; o >>= 1) sacc += __shfl_xor_sync(0xffffffffu, sacc, o);
    if (l == 0) smr[w] = sacc;
    __syncthreads();
    if (tid < 32) {
        float t = (tid < 8) ? smr[tid] : 0.f;
        #pragma unroll
        for (int o = 4; o > 0; o >>= 1) t += __shfl_xor_sync(0xffffffffu, t, o);
        if (tid == 0) smr[0] = t;
    }
    __syncthreads();
    const float inv = 1.0f / smr[0];
    #pragma unroll
    for (int u = 0; u < 8; ++u) v[u] *= inv;

    if (vec) {
        *(float4*)(r + i0)     = make_float4(v[0], v[1], v[2], v[3]);
        *(float4*)(r + i0 + 4) = make_float4(v[4], v[5], v[6], v[7]);
        uint4 hw;
        hw.x = ph2(v[0], v[1]); hw.y = ph2(v[2], v[3]);
        hw.z = ph2(v[4], v[5]); hw.w = ph2(v[6], v[7]);
        *(uint4*)(r16 + i0) = hw;
    } else {
        #pragma unroll
        for (int u = 0; u < 8; ++u) {
            int i = u * 256 + tid;
            r16[i] = __float2half_rn(v[u]);      // pad cols (i>=Sk) write 0
            if (i < Sk) r[i] = v[u];
        }
    }
}

// ---------------------------------------------------------------------------
// K3: O = P @ V via fp16 mma.sync; P and V staged with cp.async from padded
// fp16 scratch. poi fuses cross term (rows shifted -1).
// ---------------------------------------------------------------------------
__global__ __launch_bounds__(256, 2) void pv_kernel(float* __restrict__ out)
{
    __shared__ __align__(16) __half A1s[128][72];
    __shared__ __align__(16) __half A2s[128][72];
    __shared__ __align__(16) __half Vss[64][72];

    const int tid = threadIdx.x, lid = tid & 31, wid = tid >> 5;
    const int z = blockIdx.z, jt = z >> 4, bh = z & 15;
    const int m0 = blockIdx.x * 128;

    const __half* P1h = g_p + ((size_t)(jt * 16 + bh) << 22);
    const __half* P2h = g_p + ((size_t)(16 + bh) << 22);
    const __half* P3h = g_p + ((size_t)(32 + bh) << 22);
    const __half* Vh  = g_v + ((size_t)(jt * 16 + bh) << 17);   // [2048][64]

    float* O;
    int Sq;
    if (jt == 0)      { O = out + O_POI  + (size_t)bh * S_  * 64; Sq = S_;  }
    else if (jt == 1) { O = out + O_TIME + (size_t)bh * SM_ * 64; Sq = SM_; }
    else              { O = out + O_DIST + (size_t)bh * SM_ * 64; Sq = SM_; }

    const uint32_t uA1 = smem_u32(A1s), uA2 = smem_u32(A2s), uV = smem_u32(Vss);
    const int wm = wid & 3, wn = wid >> 2;

    float acc[8][4];
    #pragma unroll
    for (int t = 0; t < 8; ++t)
        #pragma unroll
        for (int j = 0; j < 4; ++j) acc[t][j] = 0.f;

    for (int ck = 0; ck < 2048; ck += 64) {
        // P1 tile via cp.async: 128 rows x 8 chunks(16B)
        #pragma unroll
        for (int it = 0; it < 4; ++it) {
            int i = it * 256 + tid;
            int row = i >> 3, c8 = i & 7;
            cpa16(uA1 + row * 144 + c8 * 16,
                  P1h + (((size_t)(m0 + row)) << 11) + ck + c8 * 8);
        }
        // V tile via cp.async: 64 rows x 8 chunks
        #pragma unroll
        for (int it = 0; it < 2; ++it) {
            int i = it * 256 + tid;
            int row = i >> 3, c8 = i & 7;
            cpa16(uV + row * 144 + c8 * 16,
                  Vh + (size_t)(ck + row) * 64 + c8 * 8);
        }
        // cross tile (manual: needs add)
        if (jt == 0) {
            #pragma unroll
            for (int it = 0; it < 4; ++it) {
                int i = it * 256 + tid;
                int row = i >> 3, col8 = (i & 7) << 3;
                uint4 res = make_uint4(0, 0, 0, 0);
                if (m0 + row > 0) {
                    size_t off = (((size_t)(m0 + row - 1)) << 11) + ck + col8;
                    uint4 a = *(const uint4*)(P2h + off);
                    uint4 b = *(const uint4*)(P3h + off);
                    __half2* ah = (__half2*)&a; __half2* bh2 = (__half2*)&b;
                    __half2* rh = (__half2*)&res;
                    #pragma unroll
                    for (int j = 0; j < 4; ++j) rh[j] = __hadd2(ah[j], bh2[j]);
                }
                *(uint4*)&A2s[row][col8] = res;
            }
        }
        cpa_wait();
        __syncthreads();

        #pragma unroll
        for (int ks = 0; ks < 4; ++ks) {
            uint32_t b[4][2];
            #pragma unroll
            for (int nb2 = 0; nb2 < 2; ++nb2) {
                int krow = ks * 16 + (((lid >> 3) & 1) << 3) + (lid & 7);
                int ncol = wn * 32 + nb2 * 16 + ((lid >> 4) << 3);
                uint32_t r4[4];
                ldm4t(r4, uV + krow * 144 + ncol * 2);
                b[nb2 * 2][0] = r4[0]; b[nb2 * 2][1] = r4[1];
                b[nb2 * 2 + 1][0] = r4[2]; b[nb2 * 2 + 1][1] = r4[3];
            }
            uint32_t a[2][4];
            #pragma unroll
            for (int mi = 0; mi < 2; ++mi) {
                int row = wm * 32 + mi * 16 + (lid & 15);
                ldm4(a[mi], uA1 + row * 144 + ks * 32 + ((lid >> 4) << 4));
            }
            #pragma unroll
            for (int mi = 0; mi < 2; ++mi)
                #pragma unroll
                for (int nj = 0; nj < 4; ++nj)
                    mma_f16(acc[mi * 4 + nj], a[mi], b[nj]);
            if (jt == 0) {
                #pragma unroll
                for (int mi = 0; mi < 2; ++mi) {
                    int row = wm * 32 + mi * 16 + (lid & 15);
                    ldm4(a[mi], uA2 + row * 144 + ks * 32 + ((lid >> 4) << 4));
                }
                #pragma unroll
                for (int mi = 0; mi < 2; ++mi)
                    #pragma unroll
                    for (int nj = 0; nj < 4; ++nj)
                        mma_f16(acc[mi * 4 + nj], a[mi], b[nj]);
            }
        }
        __syncthreads();
    }

    const int lrow = lid >> 2, lcol = (lid & 3) * 2;
    #pragma unroll
    for (int mi = 0; mi < 2; ++mi) {
        #pragma unroll
        for (int h = 0; h < 2; ++h) {
            int r = m0 + wm * 32 + mi * 16 + h * 8 + lrow;
            if (r >= Sq) continue;
            float* orow = O + (size_t)r * 64;
            #pragma unroll
            for (int nj = 0; nj < 4; ++nj) {
                int cg = wn * 32 + nj * 8 + lcol;
                *(float2*)(orow + cg) =
                    make_float2(acc[mi * 4 + nj][h * 2], acc[mi * 4 + nj][h * 2 + 1]);
            }
        }
    }
}

// ---------------------------------------------------------------------------
extern "C" void kernel_launch(void* const* d_in, const int* in_sizes, int n_in,
                              void* d_out, int out_size)
{
    const float* pq  = (const float*)d_in[0];
    const float* pk  = (const float*)d_in[1];
    const float* pvv = (const float*)d_in[2];
    const float* tq  = (const float*)d_in[3];
    const float* tk  = (const float*)d_in[4];
    const float* tvv = (const float*)d_in[5];
    const float* dq  = (const float*)d_in[6];
    const float* dk  = (const float*)d_in[7];
    const float* dvv = (const float*)d_in[8];
    const int*   msk = (const int*)d_in[9];
    float* out = (float*)d_out;

    cudaFuncSetAttribute(qk_kernel, cudaFuncAttributeMaxDynamicSharedMemorySize, 69632);

    convert_kernel<<<6144, 256>>>(pq, pk, pvv, tq, tk, tvv, dq, dk, dvv);
    qk_kernel<<<dim3(16, 16, 48), 256, 69632>>>(msk, out);
    softmax_kernel<<<dim3(2048, 48), 256>>>(out);
    pv_kernel<<<dim3(16, 1, 48), 256>>>(out);
}